// round 8
// baseline (speedup 1.0000x reference)
#include <cuda_runtime.h>
#include <cstdint>
#include <cstddef>

#define BATCH 32
#define CIN   256
#define HW    3136
#define WIMG  56
#define NTOK  49
#define OCH   768

// Scratch: conv output, pixel-major [b][p][o] ; o: 0..511 = qk, 512..767 = v(relu)
__device__ float g_buf[(size_t)BATCH * HW * OCH];
// Attention output scratch, pixel-major [b][p][256], one per partition
__device__ float o_r[(size_t)BATCH * HW * 256];
__device__ float o_c[(size_t)BATCH * HW * 256];

__device__ __forceinline__ uint32_t f2tf32(float f) {
    uint32_t u;
    asm("cvt.rna.tf32.f32 %0, %1;" : "=r"(u) : "f"(f));
    return u;
}

__device__ __forceinline__ void mma_tf32(float* c, const uint32_t* a, const uint32_t* b) {
    asm volatile(
        "mma.sync.aligned.m16n8k8.row.col.f32.tf32.tf32.f32 "
        "{%0,%1,%2,%3}, {%4,%5,%6,%7}, {%8,%9}, {%0,%1,%2,%3};"
        : "+f"(c[0]), "+f"(c[1]), "+f"(c[2]), "+f"(c[3])
        : "r"(a[0]), "r"(a[1]), "r"(a[2]), "r"(a[3]), "r"(b[0]), "r"(b[1]));
}

// ---------------------------------------------------------------------------
// Kernel 1: fused 1x1 convs as tf32 tensor-core GEMM
//   C[768,3136] = W[768,256] @ X[256,3136]  per batch
// Block tile 128(m) x 256(n), warp tile 64x64 (8 warps, 2m x 4n).
// K chunks of 32, double-buffered smem. 0.168 B/MAC crossbar traffic.
// ---------------------------------------------------------------------------
#define KC    32
#define ASP   136          // A smem row stride (mod 32 == 8 -> conflict-free)
#define BSP   264          // B smem row stride (mod 32 == 8 -> conflict-free)
#define ABUFA (KC * ASP)   // 4352
#define ABUFB (KC * BSP)   // 8448
#define CONV_SMEM_BYTES ((2 * ABUFA + 2 * ABUFB) * 4)   // 102400

__global__ __launch_bounds__(256, 1) void conv_kernel(
    const float* __restrict__ x,
    const float* __restrict__ qk_w,
    const float* __restrict__ v_w)
{
    extern __shared__ uint32_t smem[];
    uint32_t* As = smem;                     // [2][KC][ASP]
    uint32_t* Bs = smem + 2 * ABUFA;         // [2][KC][BSP]

    const int b  = blockIdx.z;
    const int m0 = blockIdx.y * 128;
    const int n0 = blockIdx.x * 256;

    const int tid  = threadIdx.x;
    const int lane = tid & 31;
    const int wid  = tid >> 5;
    const int g    = lane >> 2;
    const int tig  = lane & 3;
    const int wm   = (wid >> 2) * 64;   // 0 or 64
    const int wn   = (wid & 3) * 64;    // 0,64,128,192

    // A loader: row mA, k = kq*16 + q*4
    const int mA = tid & 127;
    const int kq = tid >> 7;
    const int am = m0 + mA;
    const float* wptr = (am < 512) ? (qk_w + (size_t)am * 256)
                                   : (v_w + (size_t)(am - 512) * 256);
    // B loader: n = nIdx (4 floats), k rows kr + 4j (j=0..7)
    const int nIdx = (tid & 63) * 4;
    const int kr   = tid >> 6;               // 0..3
    const int nB   = n0 + nIdx;
    const float* xptr = x + (size_t)b * CIN * HW + nB;
    const bool nOK = (nB < HW);              // HW % 4 == 0

    float acc[4][8][4];
#pragma unroll
    for (int mm = 0; mm < 4; ++mm)
#pragma unroll
        for (int nt = 0; nt < 8; ++nt)
#pragma unroll
            for (int r = 0; r < 4; ++r) acc[mm][nt][r] = 0.f;

    float4 avr[4], bvr[8];
    auto load_chunk = [&](int k0) {
#pragma unroll
        for (int q = 0; q < 4; ++q)
            avr[q] = *reinterpret_cast<const float4*>(wptr + k0 + kq * 16 + q * 4);
#pragma unroll
        for (int j = 0; j < 8; ++j) {
            if (nOK) bvr[j] = *reinterpret_cast<const float4*>(xptr + (size_t)(k0 + kr + 4 * j) * HW);
            else     bvr[j] = make_float4(0.f, 0.f, 0.f, 0.f);
        }
    };
    auto store_chunk = [&](int buf) {
        uint32_t* Ab = As + buf * ABUFA;
        uint32_t* Bb = Bs + buf * ABUFB;
#pragma unroll
        for (int q = 0; q < 4; ++q) {
            const int kk = kq * 16 + q * 4;
            Ab[(kk + 0) * ASP + mA] = f2tf32(avr[q].x);
            Ab[(kk + 1) * ASP + mA] = f2tf32(avr[q].y);
            Ab[(kk + 2) * ASP + mA] = f2tf32(avr[q].z);
            Ab[(kk + 3) * ASP + mA] = f2tf32(avr[q].w);
        }
#pragma unroll
        for (int j = 0; j < 8; ++j) {
            uint4 t;
            t.x = f2tf32(bvr[j].x);
            t.y = f2tf32(bvr[j].y);
            t.z = f2tf32(bvr[j].z);
            t.w = f2tf32(bvr[j].w);
            *reinterpret_cast<uint4*>(&Bb[(kr + 4 * j) * BSP + nIdx]) = t;
        }
    };

    load_chunk(0);
    store_chunk(0);
    __syncthreads();

    int cur = 0;
    for (int k0 = 0; k0 < 256; k0 += KC) {
        const bool more = (k0 + KC < 256);
        if (more) load_chunk(k0 + KC);

        const uint32_t* Ab = As + cur * ABUFA;
        const uint32_t* Bb = Bs + cur * ABUFB;
#pragma unroll
        for (int kc = 0; kc < 4; ++kc) {
            const int k8 = kc * 8;
            uint32_t a[4][4], bb[8][2];
#pragma unroll
            for (int mm = 0; mm < 4; ++mm) {
                const int row = wm + mm * 16 + g;
                a[mm][0] = Ab[(k8 + tig) * ASP + row];
                a[mm][1] = Ab[(k8 + tig) * ASP + row + 8];
                a[mm][2] = Ab[(k8 + tig + 4) * ASP + row];
                a[mm][3] = Ab[(k8 + tig + 4) * ASP + row + 8];
            }
#pragma unroll
            for (int nt = 0; nt < 8; ++nt) {
                const int col = wn + nt * 8 + g;
                bb[nt][0] = Bb[(k8 + tig) * BSP + col];
                bb[nt][1] = Bb[(k8 + tig + 4) * BSP + col];
            }
#pragma unroll
            for (int mm = 0; mm < 4; ++mm)
#pragma unroll
                for (int nt = 0; nt < 8; ++nt)
                    mma_tf32(acc[mm][nt], a[mm], bb[nt]);
        }

        if (more) store_chunk(cur ^ 1);
        __syncthreads();
        cur ^= 1;
    }

    const bool isv = (m0 >= 512);
#pragma unroll
    for (int mm = 0; mm < 4; ++mm) {
#pragma unroll
        for (int nt = 0; nt < 8; ++nt) {
            const int ncol = n0 + wn + nt * 8 + 2 * tig;
            const int mrow = m0 + wm + mm * 16 + g;
            float v0 = acc[mm][nt][0];
            float v1 = acc[mm][nt][1];
            float v2 = acc[mm][nt][2];
            float v3 = acc[mm][nt][3];
            if (isv) {
                v0 = fmaxf(v0, 0.f); v1 = fmaxf(v1, 0.f);
                v2 = fmaxf(v2, 0.f); v3 = fmaxf(v3, 0.f);
            }
            if (ncol < HW) {
                float* d0 = g_buf + ((size_t)b * HW + ncol) * OCH + mrow;
                d0[0] = v0;
                d0[8] = v2;
            }
            if (ncol + 1 < HW) {
                float* d1 = g_buf + ((size_t)b * HW + ncol + 1) * OCH + mrow;
                d1[0] = v1;
                d1[8] = v3;
            }
        }
    }
}

// ---------------------------------------------------------------------------
// Kernel 2: tf32 tensor-core window attention, both partitions in one launch.
// Block = (win, h|part<<2, b), 128 threads = 4 warps, one m16 row-tile each.
// cp.async staging, then in-place rna tf32 conversion (unbiased rounding).
// Output written pixel-major to o_r / o_c (fully coalesced).
// ---------------------------------------------------------------------------
#define QS 68
#define VS 72
#define SST 60

#define OFF_Q 0
#define OFF_K (OFF_Q + 64 * QS)
#define OFF_V (OFF_K + 56 * QS)
#define OFF_S (OFF_V + 56 * VS)
#define OFF_P (OFF_S + 64 * SST)
#define ATTN_SMEM_BYTES ((OFF_P + NTOK) * 4 + 12)

__global__ __launch_bounds__(128) void attn_kernel()
{
    extern __shared__ float sm[];
    float* s_q = sm + OFF_Q;
    float* s_k = sm + OFF_K;
    float* s_v = sm + OFF_V;
    float* s_S = sm + OFF_S;
    int*   s_p = reinterpret_cast<int*>(sm + OFF_P);

    const int b    = blockIdx.z;
    const int h    = blockIdx.y & 3;
    const int part = blockIdx.y >> 2;
    const int win  = blockIdx.x;
    const int j1   = win >> 3;
    const int j2   = win & 7;
    const int tid  = threadIdx.x;
    const int lane = tid & 31;
    const int wid  = tid >> 5;
    const int g    = lane >> 2;
    const int tig  = lane & 3;
    const int wr   = wid * 16;

    if (tid < NTOK) {
        int h1 = tid / 7, w1 = tid - h1 * 7;
        int hh, ww;
        if (part == 0) { hh = h1 * 8 + j1; ww = w1 * 8 + j2; }   // remote
        else           { hh = j1 * 7 + h1; ww = j2 * 7 + w1; }   // close
        s_p[tid] = hh * WIMG + ww;
    }
    // zero V pad rows (pad P cols are exact zeros but NaN*0=NaN -> must zero V)
    for (int i = tid; i < 7 * VS; i += 128) s_v[49 * VS + i] = 0.f;
    __syncthreads();

    // ---- stage q,k,v via cp.async: 49 pixels x 3 segs x 16 float4 ----
    {
        const float* base = g_buf + (size_t)b * HW * OCH + h * 64;
        for (int idx = tid; idx < NTOK * 48; idx += 128) {
            const int pix = idx / 48;
            const int r   = idx - pix * 48;
            const int seg = r >> 4;          // 0=q,1=k,2=v
            const int d4  = r & 15;
            const float* src = base + (size_t)s_p[pix] * OCH + seg * 256 + d4 * 4;
            float* dstf = (seg == 0 ? s_q + pix * QS
                         : seg == 1 ? s_k + pix * QS
                                    : s_v + pix * VS) + d4 * 4;
            uint32_t dsta = (uint32_t)__cvta_generic_to_shared(dstf);
            asm volatile("cp.async.ca.shared.global [%0], [%1], 16;\n"
                         :: "r"(dsta), "l"(src));
        }
        asm volatile("cp.async.commit_group;\n");
        asm volatile("cp.async.wait_group 0;\n" ::: "memory");
    }
    __syncthreads();

    // ---- in-place rna tf32 conversion (restores unbiased rounding) ----
    for (int idx = tid; idx < NTOK * 48; idx += 128) {
        const int pix = idx / 48;
        const int r   = idx - pix * 48;
        const int seg = r >> 4;
        const int d4  = r & 15;
        float* p = (seg == 0 ? s_q + pix * QS
                  : seg == 1 ? s_k + pix * QS
                             : s_v + pix * VS) + d4 * 4;
        float4 v = *reinterpret_cast<const float4*>(p);
        uint4 t;
        t.x = f2tf32(v.x); t.y = f2tf32(v.y);
        t.z = f2tf32(v.z); t.w = f2tf32(v.w);
        *reinterpret_cast<uint4*>(p) = t;
    }
    __syncthreads();

    // ---- S = Q K^T * scale ----
    {
        const uint32_t* q32 = reinterpret_cast<const uint32_t*>(s_q);
        const uint32_t* k32 = reinterpret_cast<const uint32_t*>(s_k);
        float cS[7][4];
#pragma unroll
        for (int nt = 0; nt < 7; ++nt)
#pragma unroll
            for (int r = 0; r < 4; ++r) cS[nt][r] = 0.f;

#pragma unroll
        for (int k8 = 0; k8 < 8; ++k8) {
            const int k = k8 * 8;
            uint32_t a[4];
            a[0] = q32[(wr + g) * QS + k + tig];
            a[1] = q32[(wr + g + 8) * QS + k + tig];
            a[2] = q32[(wr + g) * QS + k + tig + 4];
            a[3] = q32[(wr + g + 8) * QS + k + tig + 4];
#pragma unroll
            for (int nt = 0; nt < 7; ++nt) {
                uint32_t bf[2];
                bf[0] = k32[(nt * 8 + g) * QS + k + tig];
                bf[1] = k32[(nt * 8 + g) * QS + k + tig + 4];
                mma_tf32(cS[nt], a, bf);
            }
        }
#pragma unroll
        for (int nt = 0; nt < 7; ++nt) {
            float* S0 = s_S + (wr + g) * SST + nt * 8 + 2 * tig;
            float* S1 = s_S + (wr + g + 8) * SST + nt * 8 + 2 * tig;
            S0[0] = cS[nt][0] * 0.125f;
            S0[1] = cS[nt][1] * 0.125f;
            S1[0] = cS[nt][2] * 0.125f;
            S1[1] = cS[nt][3] * 0.125f;
        }
    }
    __syncthreads();

    // ---- softmax rows 0..48; write probs as rna tf32; zero pad cols ----
    for (int row = wid; row < NTOK; row += 4) {
        float* Srow = s_S + row * SST;
        float v0 = Srow[lane];
        float v1 = (lane < 17) ? Srow[lane + 32] : -3.0e38f;
        float m = fmaxf(v0, v1);
#pragma unroll
        for (int off = 16; off; off >>= 1) m = fmaxf(m, __shfl_xor_sync(0xffffffffu, m, off));
        float e0 = __expf(v0 - m);
        float e1 = (lane < 17) ? __expf(v1 - m) : 0.f;
        float s = e0 + e1;
#pragma unroll
        for (int off = 16; off; off >>= 1) s += __shfl_xor_sync(0xffffffffu, s, off);
        const float inv = 1.f / s;
        Srow[lane] = __uint_as_float(f2tf32(e0 * inv));
        if (lane < 17)      Srow[lane + 32] = __uint_as_float(f2tf32(e1 * inv));
        else if (lane < 24) Srow[lane + 32] = 0.f;   // cols 49..55
    }
    __syncthreads();

    // ---- O = P V ----
    {
        const uint32_t* p32 = reinterpret_cast<const uint32_t*>(s_S);
        const uint32_t* v32 = reinterpret_cast<const uint32_t*>(s_v);
        float cO[8][4];
#pragma unroll
        for (int nt = 0; nt < 8; ++nt)
#pragma unroll
            for (int r = 0; r < 4; ++r) cO[nt][r] = 0.f;

#pragma unroll
        for (int k7 = 0; k7 < 7; ++k7) {
            const int j = k7 * 8;
            uint32_t a[4];
            a[0] = p32[(wr + g) * SST + j + tig];
            a[1] = p32[(wr + g + 8) * SST + j + tig];
            a[2] = p32[(wr + g) * SST + j + tig + 4];
            a[3] = p32[(wr + g + 8) * SST + j + tig + 4];
#pragma unroll
            for (int nt = 0; nt < 8; ++nt) {
                uint32_t bf[2];
                bf[0] = v32[(j + tig) * VS + nt * 8 + g];
                bf[1] = v32[(j + tig + 4) * VS + nt * 8 + g];
                mma_tf32(cO[nt], a, bf);
            }
        }

        float* obuf = (part == 0) ? o_r : o_c;
        const int r0 = wr + g;
        const int r1 = r0 + 8;
#pragma unroll
        for (int nt = 0; nt < 8; ++nt) {
            const int d = h * 64 + nt * 8 + 2 * tig;
            if (r0 < NTOK) {
                float2 val = make_float2(cO[nt][0], cO[nt][1]);
                *reinterpret_cast<float2*>(&obuf[((size_t)b * HW + s_p[r0]) * 256 + d]) = val;
            }
            if (r1 < NTOK) {
                float2 val = make_float2(cO[nt][2], cO[nt][3]);
                *reinterpret_cast<float2*>(&obuf[((size_t)b * HW + s_p[r1]) * 256 + d]) = val;
            }
        }
    }
}

// ---------------------------------------------------------------------------
// Kernel 3: merge + transpose: out[b][c][p] = o_r[b][p][c] + o_c[b][p][c]
// ---------------------------------------------------------------------------
__global__ __launch_bounds__(256) void merge_kernel(float* __restrict__ out)
{
    __shared__ float tile[32][33];
    const int b  = blockIdx.z;
    const int c0 = blockIdx.y * 32;
    const int p0 = blockIdx.x * 32;
    const int tx = threadIdx.x & 31;
    const int ty = threadIdx.x >> 5;

#pragma unroll
    for (int i = 0; i < 4; ++i) {
        const int p = p0 + ty + i * 8;
        const size_t off = ((size_t)b * HW + p) * 256 + c0 + tx;
        tile[ty + i * 8][tx] = o_r[off] + o_c[off];
    }
    __syncthreads();
#pragma unroll
    for (int i = 0; i < 4; ++i) {
        const int c = c0 + ty + i * 8;
        out[((size_t)b * 256 + c) * HW + p0 + tx] = tile[tx][ty + i * 8];
    }
}

// ---------------------------------------------------------------------------
extern "C" void kernel_launch(void* const* d_in, const int* in_sizes, int n_in,
                              void* d_out, int out_size)
{
    const float* x    = (const float*)d_in[0];
    const float* qk_w = (const float*)d_in[1];
    const float* v_w  = (const float*)d_in[2];
    float* out = (float*)d_out;

    cudaFuncSetAttribute(conv_kernel, cudaFuncAttributeMaxDynamicSharedMemorySize, CONV_SMEM_BYTES);
    conv_kernel<<<dim3(13, 6, 32), 256, CONV_SMEM_BYTES>>>(x, qk_w, v_w);

    cudaFuncSetAttribute(attn_kernel, cudaFuncAttributeMaxDynamicSharedMemorySize, ATTN_SMEM_BYTES);
    attn_kernel<<<dim3(64, 8, 32), 128, ATTN_SMEM_BYTES>>>();

    merge_kernel<<<dim3(98, 8, 32), 256>>>(out);
}

// round 12
// speedup vs baseline: 1.1059x; 1.1059x over previous
#include <cuda_runtime.h>
#include <cstdint>
#include <cstddef>

#define BATCH 32
#define CIN   256
#define HW    3136
#define WIMG  56
#define NTOK  49
#define OCH   768

// Scratch: conv output (tf32-rounded), pixel-major [b][p][o] ; 0..511 qk, 512..767 v(relu)
__device__ float g_buf[(size_t)BATCH * HW * OCH];
// Attention output scratch, pixel-major [b][p][256], one per partition
__device__ float o_r[(size_t)BATCH * HW * 256];
__device__ float o_c[(size_t)BATCH * HW * 256];

__device__ __forceinline__ uint32_t f2tf32(float f) {
    uint32_t u;
    asm("cvt.rna.tf32.f32 %0, %1;" : "=r"(u) : "f"(f));
    return u;
}

__device__ __forceinline__ void mma_tf32(float* c, const uint32_t* a, const uint32_t* b) {
    asm volatile(
        "mma.sync.aligned.m16n8k8.row.col.f32.tf32.tf32.f32 "
        "{%0,%1,%2,%3}, {%4,%5,%6,%7}, {%8,%9}, {%0,%1,%2,%3};"
        : "+f"(c[0]), "+f"(c[1]), "+f"(c[2]), "+f"(c[3])
        : "r"(a[0]), "r"(a[1]), "r"(a[2]), "r"(a[3]), "r"(b[0]), "r"(b[1]));
}

// ---------------------------------------------------------------------------
// Kernel 1: fused 1x1 convs as tf32 tensor-core GEMM
//   C[768,3136] = W[768,256] @ X[256,3136]  per batch
// Block tile 128(m) x 256(n), warp tile 64x64 (8 warps, 2m x 4n).
// cp.async double-buffered staging (wait_group 1 overlap); rna tf32 cvt
// happens in the fragment loads. Epilogue rounds outputs to tf32 so the
// attention kernel can feed raw bits to mma exactly.
// A smem [m=128][36] (word ≡ 4g+tig mod 32 -> conflict-free),
// B smem [k=32][264]  (word ≡ 8tig+g  mod 32 -> conflict-free).
// ---------------------------------------------------------------------------
#define KC    32
#define ASPM  36
#define BSP   264
#define ABUFA (128 * ASPM)   // 4608 words
#define ABUFB (KC * BSP)     // 8448 words
#define CONV_SMEM_BYTES ((2 * ABUFA + 2 * ABUFB) * 4)   // 104448 B

__global__ __launch_bounds__(256, 1) void conv_kernel(
    const float* __restrict__ x,
    const float* __restrict__ qk_w,
    const float* __restrict__ v_w)
{
    extern __shared__ float smemf[];
    float* As = smemf;                    // [2][128][ASPM]
    float* Bs = smemf + 2 * ABUFA;        // [2][KC][BSP]

    const int b  = blockIdx.z;
    const int m0 = blockIdx.y * 128;
    const int n0 = blockIdx.x * 256;

    const int tid  = threadIdx.x;
    const int lane = tid & 31;
    const int wid  = tid >> 5;
    const int g    = lane >> 2;
    const int tig  = lane & 3;
    const int wm   = (wid >> 2) * 64;   // 0 or 64
    const int wn   = (wid & 3) * 64;    // 0,64,128,192

    // A loader: row mA, k cols kq*16 + q*4
    const int mA = tid & 127;
    const int kq = tid >> 7;
    const int am = m0 + mA;
    const float* wptr = (am < 512) ? (qk_w + (size_t)am * 256)
                                   : (v_w + (size_t)(am - 512) * 256);
    // B loader: n = nIdx (4 floats), k rows kr + 4j (j=0..7)
    const int nIdx = (tid & 63) * 4;
    const int kr   = tid >> 6;            // 0..3
    const int nB   = n0 + nIdx;
    const float* xptr = x + (size_t)b * CIN * HW + nB;
    const int bsz = (nB < HW) ? 16 : 0;   // zero-fill OOB columns

    float acc[4][8][4];
#pragma unroll
    for (int mm = 0; mm < 4; ++mm)
#pragma unroll
        for (int nt = 0; nt < 8; ++nt)
#pragma unroll
            for (int r = 0; r < 4; ++r) acc[mm][nt][r] = 0.f;

    auto issue_chunk = [&](int k0, int buf) {
        // A: 4 x 16B per thread
        float* Ab = As + buf * ABUFA + mA * ASPM;
#pragma unroll
        for (int q = 0; q < 4; ++q) {
            const int kk = kq * 16 + q * 4;
            uint32_t dsta = (uint32_t)__cvta_generic_to_shared(Ab + kk);
            asm volatile("cp.async.ca.shared.global [%0], [%1], 16;\n"
                         :: "r"(dsta), "l"(wptr + k0 + kk));
        }
        // B: 8 x 16B per thread
        float* Bb = Bs + buf * ABUFB + nIdx;
#pragma unroll
        for (int j = 0; j < 8; ++j) {
            const int kk = kr + 4 * j;
            uint32_t dsta = (uint32_t)__cvta_generic_to_shared(Bb + kk * BSP);
            asm volatile("cp.async.ca.shared.global [%0], [%1], 16, %2;\n"
                         :: "r"(dsta), "l"(xptr + (size_t)(k0 + kk) * HW), "r"(bsz));
        }
        asm volatile("cp.async.commit_group;\n");
    };

    issue_chunk(0, 0);

    int cur = 0;
    for (int k0 = 0; k0 < 256; k0 += KC) {
        const bool more = (k0 + KC < 256);
        if (more) issue_chunk(k0 + KC, cur ^ 1);

        if (more) asm volatile("cp.async.wait_group 1;\n" ::: "memory");
        else      asm volatile("cp.async.wait_group 0;\n" ::: "memory");
        __syncthreads();

        const float* Af = As + cur * ABUFA;
        const float* Bf = Bs + cur * ABUFB;
#pragma unroll
        for (int kc = 0; kc < 4; ++kc) {
            const int k8 = kc * 8;
            uint32_t a[4][4], bb[8][2];
#pragma unroll
            for (int mm = 0; mm < 4; ++mm) {
                const int row = wm + mm * 16 + g;
                a[mm][0] = f2tf32(Af[row * ASPM + k8 + tig]);
                a[mm][1] = f2tf32(Af[(row + 8) * ASPM + k8 + tig]);
                a[mm][2] = f2tf32(Af[row * ASPM + k8 + tig + 4]);
                a[mm][3] = f2tf32(Af[(row + 8) * ASPM + k8 + tig + 4]);
            }
#pragma unroll
            for (int nt = 0; nt < 8; ++nt) {
                const int col = wn + nt * 8 + g;
                bb[nt][0] = f2tf32(Bf[(k8 + tig) * BSP + col]);
                bb[nt][1] = f2tf32(Bf[(k8 + tig + 4) * BSP + col]);
            }
#pragma unroll
            for (int mm = 0; mm < 4; ++mm)
#pragma unroll
                for (int nt = 0; nt < 8; ++nt)
                    mma_tf32(acc[mm][nt], a[mm], bb[nt]);
        }
        __syncthreads();   // all reads of 'cur' done before next issue overwrites it
        cur ^= 1;
    }

    // ---- epilogue: relu (v rows), round to tf32, scatter pixel-major ----
    const bool isv = (m0 >= 512);
#pragma unroll
    for (int mm = 0; mm < 4; ++mm) {
#pragma unroll
        for (int nt = 0; nt < 8; ++nt) {
            const int ncol = n0 + wn + nt * 8 + 2 * tig;
            const int mrow = m0 + wm + mm * 16 + g;
            float v0 = acc[mm][nt][0];
            float v1 = acc[mm][nt][1];
            float v2 = acc[mm][nt][2];
            float v3 = acc[mm][nt][3];
            if (isv) {
                v0 = fmaxf(v0, 0.f); v1 = fmaxf(v1, 0.f);
                v2 = fmaxf(v2, 0.f); v3 = fmaxf(v3, 0.f);
            }
            v0 = __uint_as_float(f2tf32(v0));
            v1 = __uint_as_float(f2tf32(v1));
            v2 = __uint_as_float(f2tf32(v2));
            v3 = __uint_as_float(f2tf32(v3));
            if (ncol < HW) {
                float* d0 = g_buf + ((size_t)b * HW + ncol) * OCH + mrow;
                d0[0] = v0;
                d0[8] = v2;
            }
            if (ncol + 1 < HW) {
                float* d1 = g_buf + ((size_t)b * HW + ncol + 1) * OCH + mrow;
                d1[0] = v1;
                d1[8] = v3;
            }
        }
    }
}

// ---------------------------------------------------------------------------
// Kernel 2: tf32 tensor-core window attention, both partitions in one launch.
// Block = (win, h|part<<2, b), 128 threads = 4 warps, one m16 row-tile each.
// cp.async staging; g_buf is already tf32-rounded, so raw bits -> mma is exact.
// Output written pixel-major to o_r / o_c (fully coalesced).
// ---------------------------------------------------------------------------
#define QS 68
#define VS 72
#define SST 60

#define OFF_Q 0
#define OFF_K (OFF_Q + 64 * QS)
#define OFF_V (OFF_K + 56 * QS)
#define OFF_S (OFF_V + 56 * VS)
#define OFF_P (OFF_S + 64 * SST)
#define ATTN_SMEM_BYTES ((OFF_P + NTOK) * 4 + 12)

__global__ __launch_bounds__(128) void attn_kernel()
{
    extern __shared__ float sm[];
    float* s_q = sm + OFF_Q;
    float* s_k = sm + OFF_K;
    float* s_v = sm + OFF_V;
    float* s_S = sm + OFF_S;
    int*   s_p = reinterpret_cast<int*>(sm + OFF_P);

    const int b    = blockIdx.z;
    const int h    = blockIdx.y & 3;
    const int part = blockIdx.y >> 2;
    const int win  = blockIdx.x;
    const int j1   = win >> 3;
    const int j2   = win & 7;
    const int tid  = threadIdx.x;
    const int lane = tid & 31;
    const int wid  = tid >> 5;
    const int g    = lane >> 2;
    const int tig  = lane & 3;
    const int wr   = wid * 16;

    if (tid < NTOK) {
        int h1 = tid / 7, w1 = tid - h1 * 7;
        int hh, ww;
        if (part == 0) { hh = h1 * 8 + j1; ww = w1 * 8 + j2; }   // remote
        else           { hh = j1 * 7 + h1; ww = j2 * 7 + w1; }   // close
        s_p[tid] = hh * WIMG + ww;
    }
    // zero V pad rows (pad P cols are exact zeros but NaN*0=NaN -> must zero V)
    for (int i = tid; i < 7 * VS; i += 128) s_v[49 * VS + i] = 0.f;
    __syncthreads();

    // ---- stage q,k,v via cp.async: 49 pixels x 3 segs x 16 float4 ----
    {
        const float* base = g_buf + (size_t)b * HW * OCH + h * 64;
        for (int idx = tid; idx < NTOK * 48; idx += 128) {
            const int pix = idx / 48;
            const int r   = idx - pix * 48;
            const int seg = r >> 4;          // 0=q,1=k,2=v
            const int d4  = r & 15;
            const float* src = base + (size_t)s_p[pix] * OCH + seg * 256 + d4 * 4;
            float* dstf = (seg == 0 ? s_q + pix * QS
                         : seg == 1 ? s_k + pix * QS
                                    : s_v + pix * VS) + d4 * 4;
            uint32_t dsta = (uint32_t)__cvta_generic_to_shared(dstf);
            asm volatile("cp.async.ca.shared.global [%0], [%1], 16;\n"
                         :: "r"(dsta), "l"(src));
        }
        asm volatile("cp.async.commit_group;\n");
        asm volatile("cp.async.wait_group 0;\n" ::: "memory");
    }
    __syncthreads();

    // ---- S = Q K^T * scale ----
    {
        const uint32_t* q32 = reinterpret_cast<const uint32_t*>(s_q);
        const uint32_t* k32 = reinterpret_cast<const uint32_t*>(s_k);
        float cS[7][4];
#pragma unroll
        for (int nt = 0; nt < 7; ++nt)
#pragma unroll
            for (int r = 0; r < 4; ++r) cS[nt][r] = 0.f;

#pragma unroll
        for (int k8 = 0; k8 < 8; ++k8) {
            const int k = k8 * 8;
            uint32_t a[4];
            a[0] = q32[(wr + g) * QS + k + tig];
            a[1] = q32[(wr + g + 8) * QS + k + tig];
            a[2] = q32[(wr + g) * QS + k + tig + 4];
            a[3] = q32[(wr + g + 8) * QS + k + tig + 4];
#pragma unroll
            for (int nt = 0; nt < 7; ++nt) {
                uint32_t bf[2];
                bf[0] = k32[(nt * 8 + g) * QS + k + tig];
                bf[1] = k32[(nt * 8 + g) * QS + k + tig + 4];
                mma_tf32(cS[nt], a, bf);
            }
        }
#pragma unroll
        for (int nt = 0; nt < 7; ++nt) {
            float* S0 = s_S + (wr + g) * SST + nt * 8 + 2 * tig;
            float* S1 = s_S + (wr + g + 8) * SST + nt * 8 + 2 * tig;
            S0[0] = cS[nt][0] * 0.125f;
            S0[1] = cS[nt][1] * 0.125f;
            S1[0] = cS[nt][2] * 0.125f;
            S1[1] = cS[nt][3] * 0.125f;
        }
    }
    __syncthreads();

    // ---- softmax rows 0..48; write probs as rna tf32; zero pad cols ----
    for (int row = wid; row < NTOK; row += 4) {
        float* Srow = s_S + row * SST;
        float v0 = Srow[lane];
        float v1 = (lane < 17) ? Srow[lane + 32] : -3.0e38f;
        float m = fmaxf(v0, v1);
#pragma unroll
        for (int off = 16; off; off >>= 1) m = fmaxf(m, __shfl_xor_sync(0xffffffffu, m, off));
        float e0 = __expf(v0 - m);
        float e1 = (lane < 17) ? __expf(v1 - m) : 0.f;
        float s = e0 + e1;
#pragma unroll
        for (int off = 16; off; off >>= 1) s += __shfl_xor_sync(0xffffffffu, s, off);
        const float inv = 1.f / s;
        Srow[lane] = __uint_as_float(f2tf32(e0 * inv));
        if (lane < 17)      Srow[lane + 32] = __uint_as_float(f2tf32(e1 * inv));
        else if (lane < 24) Srow[lane + 32] = 0.f;   // cols 49..55
    }
    __syncthreads();

    // ---- O = P V ----
    {
        const uint32_t* p32 = reinterpret_cast<const uint32_t*>(s_S);
        const uint32_t* v32 = reinterpret_cast<const uint32_t*>(s_v);
        float cO[8][4];
#pragma unroll
        for (int nt = 0; nt < 8; ++nt)
#pragma unroll
            for (int r = 0; r < 4; ++r) cO[nt][r] = 0.f;

#pragma unroll
        for (int k7 = 0; k7 < 7; ++k7) {
            const int j = k7 * 8;
            uint32_t a[4];
            a[0] = p32[(wr + g) * SST + j + tig];
            a[1] = p32[(wr + g + 8) * SST + j + tig];
            a[2] = p32[(wr + g) * SST + j + tig + 4];
            a[3] = p32[(wr + g + 8) * SST + j + tig + 4];
#pragma unroll
            for (int nt = 0; nt < 8; ++nt) {
                uint32_t bf[2];
                bf[0] = v32[(j + tig) * VS + nt * 8 + g];
                bf[1] = v32[(j + tig + 4) * VS + nt * 8 + g];
                mma_tf32(cO[nt], a, bf);
            }
        }

        float* obuf = (part == 0) ? o_r : o_c;
        const int r0 = wr + g;
        const int r1 = r0 + 8;
#pragma unroll
        for (int nt = 0; nt < 8; ++nt) {
            const int d = h * 64 + nt * 8 + 2 * tig;
            if (r0 < NTOK) {
                float2 val = make_float2(cO[nt][0], cO[nt][1]);
                *reinterpret_cast<float2*>(&obuf[((size_t)b * HW + s_p[r0]) * 256 + d]) = val;
            }
            if (r1 < NTOK) {
                float2 val = make_float2(cO[nt][2], cO[nt][3]);
                *reinterpret_cast<float2*>(&obuf[((size_t)b * HW + s_p[r1]) * 256 + d]) = val;
            }
        }
    }
}

// ---------------------------------------------------------------------------
// Kernel 3: merge + transpose: out[b][c][p] = o_r[b][p][c] + o_c[b][p][c]
// ---------------------------------------------------------------------------
__global__ __launch_bounds__(256) void merge_kernel(float* __restrict__ out)
{
    __shared__ float tile[32][33];
    const int b  = blockIdx.z;
    const int c0 = blockIdx.y * 32;
    const int p0 = blockIdx.x * 32;
    const int tx = threadIdx.x & 31;
    const int ty = threadIdx.x >> 5;

#pragma unroll
    for (int i = 0; i < 4; ++i) {
        const int p = p0 + ty + i * 8;
        const size_t off = ((size_t)b * HW + p) * 256 + c0 + tx;
        tile[ty + i * 8][tx] = o_r[off] + o_c[off];
    }
    __syncthreads();
#pragma unroll
    for (int i = 0; i < 4; ++i) {
        const int c = c0 + ty + i * 8;
        out[((size_t)b * 256 + c) * HW + p0 + tx] = tile[tx][ty + i * 8];
    }
}

// ---------------------------------------------------------------------------
extern "C" void kernel_launch(void* const* d_in, const int* in_sizes, int n_in,
                              void* d_out, int out_size)
{
    const float* x    = (const float*)d_in[0];
    const float* qk_w = (const float*)d_in[1];
    const float* v_w  = (const float*)d_in[2];
    float* out = (float*)d_out;

    cudaFuncSetAttribute(conv_kernel, cudaFuncAttributeMaxDynamicSharedMemorySize, CONV_SMEM_BYTES);
    conv_kernel<<<dim3(13, 6, 32), 256, CONV_SMEM_BYTES>>>(x, qk_w, v_w);

    cudaFuncSetAttribute(attn_kernel, cudaFuncAttributeMaxDynamicSharedMemorySize, ATTN_SMEM_BYTES);
    attn_kernel<<<dim3(64, 8, 32), 128, ATTN_SMEM_BYTES>>>();

    merge_kernel<<<dim3(98, 8, 32), 256>>>(out);
}

// round 14
// speedup vs baseline: 1.2961x; 1.1721x over previous
#include <cuda_runtime.h>
#include <cuda_fp16.h>
#include <cstdint>
#include <cstddef>

#define BATCH 32
#define CIN   256
#define HW    3136
#define WIMG  56
#define NTOK  49
#define OCH   768

// Scratch: conv output (tf32-rounded), pixel-major [b][p][o] ; 0..511 qk, 512..767 v(relu)
__device__ float g_buf[(size_t)BATCH * HW * OCH];
// Attention output scratch, pixel-major [b][p][256], one per partition
__device__ float o_r[(size_t)BATCH * HW * 256];
__device__ float o_c[(size_t)BATCH * HW * 256];

__device__ __forceinline__ uint32_t f2tf32(float f) {
    uint32_t u;
    asm("cvt.rna.tf32.f32 %0, %1;" : "=r"(u) : "f"(f));
    return u;
}

__device__ __forceinline__ uint32_t pack_f16x2(float lo, float hi) {
    uint32_t d;
    asm("cvt.rn.f16x2.f32 %0, %1, %2;" : "=r"(d) : "f"(hi), "f"(lo));
    return d;
}

__device__ __forceinline__ void mma_tf32(float* c, const uint32_t* a, const uint32_t* b) {
    asm volatile(
        "mma.sync.aligned.m16n8k8.row.col.f32.tf32.tf32.f32 "
        "{%0,%1,%2,%3}, {%4,%5,%6,%7}, {%8,%9}, {%0,%1,%2,%3};"
        : "+f"(c[0]), "+f"(c[1]), "+f"(c[2]), "+f"(c[3])
        : "r"(a[0]), "r"(a[1]), "r"(a[2]), "r"(a[3]), "r"(b[0]), "r"(b[1]));
}

__device__ __forceinline__ void mma_f16(float* c, const uint32_t* a, const uint32_t* b) {
    asm volatile(
        "mma.sync.aligned.m16n8k16.row.col.f32.f16.f16.f32 "
        "{%0,%1,%2,%3}, {%4,%5,%6,%7}, {%8,%9}, {%0,%1,%2,%3};"
        : "+f"(c[0]), "+f"(c[1]), "+f"(c[2]), "+f"(c[3])
        : "r"(a[0]), "r"(a[1]), "r"(a[2]), "r"(a[3]), "r"(b[0]), "r"(b[1]));
}

__device__ __forceinline__ void ldsm_x4(uint32_t* r, uint32_t addr) {
    asm volatile("ldmatrix.sync.aligned.m8n8.x4.shared.b16 {%0,%1,%2,%3}, [%4];"
                 : "=r"(r[0]), "=r"(r[1]), "=r"(r[2]), "=r"(r[3]) : "r"(addr));
}
__device__ __forceinline__ void ldsm_x4_t(uint32_t* r, uint32_t addr) {
    asm volatile("ldmatrix.sync.aligned.m8n8.x4.trans.shared.b16 {%0,%1,%2,%3}, [%4];"
                 : "=r"(r[0]), "=r"(r[1]), "=r"(r[2]), "=r"(r[3]) : "r"(addr));
}

// ---------------------------------------------------------------------------
// Kernel 1: fused 1x1 convs as fp16 tensor-core GEMM (fp32 accumulate)
//   C[768,3136] = W[768,256] @ X[256,3136]  per batch
// Block tile 128(m) x 256(n), warp tile 64x64 (8 warps, 2m x 4n).
// fp16 has the same 11-bit significand as tf32 -> identical accuracy here,
// 2x the mma throughput, half the smem traffic.
// A smem [m=128][40 halfs] (row = 80B; 8-row 16B segs disjoint mod 128 -> LDSM ok)
// B smem [k=32][264 halfs] (row = 528B; 528 mod 128 = 16 -> LDSM conflict-free)
// A frags: ldmatrix.x4 ; B frags: ldmatrix.x4.trans from natural [k][n] layout.
// Epilogue: relu(v), round to tf32, store fp32 g_buf (attn feeds raw bits to mma).
// ---------------------------------------------------------------------------
#define KC    32
#define ASPH  40                    // A stride (halfs)
#define BSPH  264                   // B stride (halfs)
#define ABUFH (128 * ASPH)          // 5120 halfs
#define BBUFH (KC * BSPH)           // 8448 halfs
#define CONV_SMEM_BYTES ((2 * ABUFH + 2 * BBUFH) * 2)   // 54272 B

__global__ __launch_bounds__(256, 1) void conv_kernel(
    const float* __restrict__ x,
    const float* __restrict__ qk_w,
    const float* __restrict__ v_w)
{
    extern __shared__ __half smh[];
    __half* Ah = smh;                 // [2][128][ASPH]
    __half* Bh = smh + 2 * ABUFH;     // [2][KC][BSPH]

    const int b  = blockIdx.z;
    const int m0 = blockIdx.y * 128;
    const int n0 = blockIdx.x * 256;

    const int tid  = threadIdx.x;
    const int lane = tid & 31;
    const int wid  = tid >> 5;
    const int wm   = (wid >> 2) * 64;   // 0 or 64
    const int wn   = (wid & 3) * 64;    // 0,64,128,192

    // A loader: row mA, k cols kq*16 + q*4
    const int mA = tid & 127;
    const int kq = tid >> 7;
    const int am = m0 + mA;
    const float* wptr = (am < 512) ? (qk_w + (size_t)am * 256)
                                   : (v_w + (size_t)(am - 512) * 256);
    // B loader: n = nIdx..+3, k rows kr + 4j (j=0..7)
    const int nIdx = (tid & 63) * 4;
    const int kr   = tid >> 6;            // 0..3
    const int nB   = n0 + nIdx;
    const float* xptr = x + (size_t)b * CIN * HW + nB;
    const bool nOK = (nB < HW);           // HW % 4 == 0

    float acc[4][8][4];
#pragma unroll
    for (int mm = 0; mm < 4; ++mm)
#pragma unroll
        for (int nt = 0; nt < 8; ++nt)
#pragma unroll
            for (int r = 0; r < 4; ++r) acc[mm][nt][r] = 0.f;

    float4 avr[4], bvr[8];
    auto load_chunk = [&](int k0) {
#pragma unroll
        for (int q = 0; q < 4; ++q)
            avr[q] = *reinterpret_cast<const float4*>(wptr + k0 + kq * 16 + q * 4);
#pragma unroll
        for (int j = 0; j < 8; ++j) {
            if (nOK) bvr[j] = *reinterpret_cast<const float4*>(xptr + (size_t)(k0 + kr + 4 * j) * HW);
            else     bvr[j] = make_float4(0.f, 0.f, 0.f, 0.f);
        }
    };
    auto store_chunk = [&](int buf) {
        __half* Ab = Ah + buf * ABUFH + mA * ASPH;
#pragma unroll
        for (int q = 0; q < 4; ++q) {
            const int kk = kq * 16 + q * 4;
            uint2 t;
            t.x = pack_f16x2(avr[q].x, avr[q].y);
            t.y = pack_f16x2(avr[q].z, avr[q].w);
            *reinterpret_cast<uint2*>(Ab + kk) = t;
        }
        __half* Bb = Bh + buf * BBUFH + nIdx;
#pragma unroll
        for (int j = 0; j < 8; ++j) {
            const int kk = kr + 4 * j;
            uint2 t;
            t.x = pack_f16x2(bvr[j].x, bvr[j].y);
            t.y = pack_f16x2(bvr[j].z, bvr[j].w);
            *reinterpret_cast<uint2*>(Bb + kk * BSPH) = t;
        }
    };

    load_chunk(0);
    store_chunk(0);
    __syncthreads();

    int cur = 0;
    for (int k0 = 0; k0 < 256; k0 += KC) {
        const bool more = (k0 + KC < 256);
        if (more) load_chunk(k0 + KC);

        const __half* Ab = Ah + cur * ABUFH;
        const __half* Bb = Bh + cur * BBUFH;
#pragma unroll
        for (int ks = 0; ks < 2; ++ks) {        // two k16 steps per 32-chunk
            uint32_t a[4][4];
#pragma unroll
            for (int mt = 0; mt < 4; ++mt) {
                const int row = wm + mt * 16 + (lane & 15);
                const int kh  = ks * 16 + (lane >> 4) * 8;
                ldsm_x4(a[mt], (uint32_t)__cvta_generic_to_shared(Ab + row * ASPH + kh));
            }
            uint32_t bf[8][2];
#pragma unroll
            for (int p = 0; p < 4; ++p) {
                const int r    = lane & 7;
                const int seg  = lane >> 3;               // 0..3
                const int krow = ks * 16 + (seg & 1) * 8 + r;
                const int col  = wn + p * 16 + (seg >> 1) * 8;
                uint32_t t[4];
                ldsm_x4_t(t, (uint32_t)__cvta_generic_to_shared(Bb + krow * BSPH + col));
                bf[2 * p][0]     = t[0];
                bf[2 * p][1]     = t[1];
                bf[2 * p + 1][0] = t[2];
                bf[2 * p + 1][1] = t[3];
            }
#pragma unroll
            for (int mt = 0; mt < 4; ++mt)
#pragma unroll
                for (int nt = 0; nt < 8; ++nt)
                    mma_f16(acc[mt][nt], a[mt], bf[nt]);
        }

        if (more) store_chunk(cur ^ 1);
        __syncthreads();
        cur ^= 1;
    }

    // ---- epilogue: relu (v rows), round to tf32, scatter pixel-major ----
    const int g   = lane >> 2;
    const int tig = lane & 3;
    const bool isv = (m0 >= 512);
#pragma unroll
    for (int mm = 0; mm < 4; ++mm) {
#pragma unroll
        for (int nt = 0; nt < 8; ++nt) {
            const int ncol = n0 + wn + nt * 8 + 2 * tig;
            const int mrow = m0 + wm + mm * 16 + g;
            float v0 = acc[mm][nt][0];
            float v1 = acc[mm][nt][1];
            float v2 = acc[mm][nt][2];
            float v3 = acc[mm][nt][3];
            if (isv) {
                v0 = fmaxf(v0, 0.f); v1 = fmaxf(v1, 0.f);
                v2 = fmaxf(v2, 0.f); v3 = fmaxf(v3, 0.f);
            }
            v0 = __uint_as_float(f2tf32(v0));
            v1 = __uint_as_float(f2tf32(v1));
            v2 = __uint_as_float(f2tf32(v2));
            v3 = __uint_as_float(f2tf32(v3));
            if (ncol < HW) {
                float* d0 = g_buf + ((size_t)b * HW + ncol) * OCH + mrow;
                d0[0] = v0;
                d0[8] = v2;
            }
            if (ncol + 1 < HW) {
                float* d1 = g_buf + ((size_t)b * HW + ncol + 1) * OCH + mrow;
                d1[0] = v1;
                d1[8] = v3;
            }
        }
    }
}

// ---------------------------------------------------------------------------
// Kernel 2: tf32 tensor-core window attention, both partitions in one launch.
// Block = (win, h|part<<2, b), 128 threads = 4 warps, one m16 row-tile each.
// cp.async staging; g_buf is already tf32-rounded, so raw bits -> mma is exact.
// Output written pixel-major to o_r / o_c (fully coalesced).   (unchanged)
// ---------------------------------------------------------------------------
#define QS 68
#define VS 72
#define SST 60

#define OFF_Q 0
#define OFF_K (OFF_Q + 64 * QS)
#define OFF_V (OFF_K + 56 * QS)
#define OFF_S (OFF_V + 56 * VS)
#define OFF_P (OFF_S + 64 * SST)
#define ATTN_SMEM_BYTES ((OFF_P + NTOK) * 4 + 12)

__global__ __launch_bounds__(128) void attn_kernel()
{
    extern __shared__ float sm[];
    float* s_q = sm + OFF_Q;
    float* s_k = sm + OFF_K;
    float* s_v = sm + OFF_V;
    float* s_S = sm + OFF_S;
    int*   s_p = reinterpret_cast<int*>(sm + OFF_P);

    const int b    = blockIdx.z;
    const int h    = blockIdx.y & 3;
    const int part = blockIdx.y >> 2;
    const int win  = blockIdx.x;
    const int j1   = win >> 3;
    const int j2   = win & 7;
    const int tid  = threadIdx.x;
    const int lane = tid & 31;
    const int wid  = tid >> 5;
    const int g    = lane >> 2;
    const int tig  = lane & 3;
    const int wr   = wid * 16;

    if (tid < NTOK) {
        int h1 = tid / 7, w1 = tid - h1 * 7;
        int hh, ww;
        if (part == 0) { hh = h1 * 8 + j1; ww = w1 * 8 + j2; }   // remote
        else           { hh = j1 * 7 + h1; ww = j2 * 7 + w1; }   // close
        s_p[tid] = hh * WIMG + ww;
    }
    // zero V pad rows (pad P cols are exact zeros but NaN*0=NaN -> must zero V)
    for (int i = tid; i < 7 * VS; i += 128) s_v[49 * VS + i] = 0.f;
    __syncthreads();

    // ---- stage q,k,v via cp.async: 49 pixels x 3 segs x 16 float4 ----
    {
        const float* base = g_buf + (size_t)b * HW * OCH + h * 64;
        for (int idx = tid; idx < NTOK * 48; idx += 128) {
            const int pix = idx / 48;
            const int r   = idx - pix * 48;
            const int seg = r >> 4;          // 0=q,1=k,2=v
            const int d4  = r & 15;
            const float* src = base + (size_t)s_p[pix] * OCH + seg * 256 + d4 * 4;
            float* dstf = (seg == 0 ? s_q + pix * QS
                         : seg == 1 ? s_k + pix * QS
                                    : s_v + pix * VS) + d4 * 4;
            uint32_t dsta = (uint32_t)__cvta_generic_to_shared(dstf);
            asm volatile("cp.async.ca.shared.global [%0], [%1], 16;\n"
                         :: "r"(dsta), "l"(src));
        }
        asm volatile("cp.async.commit_group;\n");
        asm volatile("cp.async.wait_group 0;\n" ::: "memory");
    }
    __syncthreads();

    // ---- S = Q K^T * scale ----
    {
        const uint32_t* q32 = reinterpret_cast<const uint32_t*>(s_q);
        const uint32_t* k32 = reinterpret_cast<const uint32_t*>(s_k);
        float cS[7][4];
#pragma unroll
        for (int nt = 0; nt < 7; ++nt)
#pragma unroll
            for (int r = 0; r < 4; ++r) cS[nt][r] = 0.f;

#pragma unroll
        for (int k8 = 0; k8 < 8; ++k8) {
            const int k = k8 * 8;
            uint32_t a[4];
            a[0] = q32[(wr + g) * QS + k + tig];
            a[1] = q32[(wr + g + 8) * QS + k + tig];
            a[2] = q32[(wr + g) * QS + k + tig + 4];
            a[3] = q32[(wr + g + 8) * QS + k + tig + 4];
#pragma unroll
            for (int nt = 0; nt < 7; ++nt) {
                uint32_t bf[2];
                bf[0] = k32[(nt * 8 + g) * QS + k + tig];
                bf[1] = k32[(nt * 8 + g) * QS + k + tig + 4];
                mma_tf32(cS[nt], a, bf);
            }
        }
#pragma unroll
        for (int nt = 0; nt < 7; ++nt) {
            float* S0 = s_S + (wr + g) * SST + nt * 8 + 2 * tig;
            float* S1 = s_S + (wr + g + 8) * SST + nt * 8 + 2 * tig;
            S0[0] = cS[nt][0] * 0.125f;
            S0[1] = cS[nt][1] * 0.125f;
            S1[0] = cS[nt][2] * 0.125f;
            S1[1] = cS[nt][3] * 0.125f;
        }
    }
    __syncthreads();

    // ---- softmax rows 0..48; write probs as rna tf32; zero pad cols ----
    for (int row = wid; row < NTOK; row += 4) {
        float* Srow = s_S + row * SST;
        float v0 = Srow[lane];
        float v1 = (lane < 17) ? Srow[lane + 32] : -3.0e38f;
        float m = fmaxf(v0, v1);
#pragma unroll
        for (int off = 16; off; off >>= 1) m = fmaxf(m, __shfl_xor_sync(0xffffffffu, m, off));
        float e0 = __expf(v0 - m);
        float e1 = (lane < 17) ? __expf(v1 - m) : 0.f;
        float s = e0 + e1;
#pragma unroll
        for (int off = 16; off; off >>= 1) s += __shfl_xor_sync(0xffffffffu, s, off);
        const float inv = 1.f / s;
        Srow[lane] = __uint_as_float(f2tf32(e0 * inv));
        if (lane < 17)      Srow[lane + 32] = __uint_as_float(f2tf32(e1 * inv));
        else if (lane < 24) Srow[lane + 32] = 0.f;   // cols 49..55
    }
    __syncthreads();

    // ---- O = P V ----
    {
        const uint32_t* p32 = reinterpret_cast<const uint32_t*>(s_S);
        const uint32_t* v32 = reinterpret_cast<const uint32_t*>(s_v);
        float cO[8][4];
#pragma unroll
        for (int nt = 0; nt < 8; ++nt)
#pragma unroll
            for (int r = 0; r < 4; ++r) cO[nt][r] = 0.f;

#pragma unroll
        for (int k7 = 0; k7 < 7; ++k7) {
            const int j = k7 * 8;
            uint32_t a[4];
            a[0] = p32[(wr + g) * SST + j + tig];
            a[1] = p32[(wr + g + 8) * SST + j + tig];
            a[2] = p32[(wr + g) * SST + j + tig + 4];
            a[3] = p32[(wr + g + 8) * SST + j + tig + 4];
#pragma unroll
            for (int nt = 0; nt < 8; ++nt) {
                uint32_t bf[2];
                bf[0] = v32[(j + tig) * VS + nt * 8 + g];
                bf[1] = v32[(j + tig + 4) * VS + nt * 8 + g];
                mma_tf32(cO[nt], a, bf);
            }
        }

        float* obuf = (part == 0) ? o_r : o_c;
        const int r0 = wr + g;
        const int r1 = r0 + 8;
#pragma unroll
        for (int nt = 0; nt < 8; ++nt) {
            const int d = h * 64 + nt * 8 + 2 * tig;
            if (r0 < NTOK) {
                float2 val = make_float2(cO[nt][0], cO[nt][1]);
                *reinterpret_cast<float2*>(&obuf[((size_t)b * HW + s_p[r0]) * 256 + d]) = val;
            }
            if (r1 < NTOK) {
                float2 val = make_float2(cO[nt][2], cO[nt][3]);
                *reinterpret_cast<float2*>(&obuf[((size_t)b * HW + s_p[r1]) * 256 + d]) = val;
            }
        }
    }
}

// ---------------------------------------------------------------------------
// Kernel 3: merge + transpose: out[b][c][p] = o_r[b][p][c] + o_c[b][p][c]
// ---------------------------------------------------------------------------
__global__ __launch_bounds__(256) void merge_kernel(float* __restrict__ out)
{
    __shared__ float tile[32][33];
    const int b  = blockIdx.z;
    const int c0 = blockIdx.y * 32;
    const int p0 = blockIdx.x * 32;
    const int tx = threadIdx.x & 31;
    const int ty = threadIdx.x >> 5;

#pragma unroll
    for (int i = 0; i < 4; ++i) {
        const int p = p0 + ty + i * 8;
        const size_t off = ((size_t)b * HW + p) * 256 + c0 + tx;
        tile[ty + i * 8][tx] = o_r[off] + o_c[off];
    }
    __syncthreads();
#pragma unroll
    for (int i = 0; i < 4; ++i) {
        const int c = c0 + ty + i * 8;
        out[((size_t)b * 256 + c) * HW + p0 + tx] = tile[tx][ty + i * 8];
    }
}

// ---------------------------------------------------------------------------
extern "C" void kernel_launch(void* const* d_in, const int* in_sizes, int n_in,
                              void* d_out, int out_size)
{
    const float* x    = (const float*)d_in[0];
    const float* qk_w = (const float*)d_in[1];
    const float* v_w  = (const float*)d_in[2];
    float* out = (float*)d_out;

    cudaFuncSetAttribute(conv_kernel, cudaFuncAttributeMaxDynamicSharedMemorySize, CONV_SMEM_BYTES);
    conv_kernel<<<dim3(13, 6, 32), 256, CONV_SMEM_BYTES>>>(x, qk_w, v_w);

    cudaFuncSetAttribute(attn_kernel, cudaFuncAttributeMaxDynamicSharedMemorySize, ATTN_SMEM_BYTES);
    attn_kernel<<<dim3(64, 8, 32), 128, ATTN_SMEM_BYTES>>>();

    merge_kernel<<<dim3(98, 8, 32), 256>>>(out);
}

// round 15
// speedup vs baseline: 1.5914x; 1.2278x over previous
#include <cuda_runtime.h>
#include <cuda_fp16.h>
#include <cstdint>
#include <cstddef>

#define BATCH 32
#define CIN   256
#define HW    3136
#define WIMG  56
#define NTOK  49
#define OCH   768

// Scratch: conv output (fp16), pixel-major [b][p][o] ; 0..511 qk, 512..767 v(relu)
__device__ __half g_buf[(size_t)BATCH * HW * OCH];
// Attention output scratch (fp16), pixel-major [b][p][256], one per partition
__device__ __half o_r[(size_t)BATCH * HW * 256];
__device__ __half o_c[(size_t)BATCH * HW * 256];

__device__ __forceinline__ uint32_t pack_f16x2(float lo, float hi) {
    uint32_t d;
    asm("cvt.rn.f16x2.f32 %0, %1, %2;" : "=r"(d) : "f"(hi), "f"(lo));
    return d;
}

__device__ __forceinline__ void mma_f16(float* c, const uint32_t* a, const uint32_t* b) {
    asm volatile(
        "mma.sync.aligned.m16n8k16.row.col.f32.f16.f16.f32 "
        "{%0,%1,%2,%3}, {%4,%5,%6,%7}, {%8,%9}, {%0,%1,%2,%3};"
        : "+f"(c[0]), "+f"(c[1]), "+f"(c[2]), "+f"(c[3])
        : "r"(a[0]), "r"(a[1]), "r"(a[2]), "r"(a[3]), "r"(b[0]), "r"(b[1]));
}

__device__ __forceinline__ void ldsm_x4(uint32_t* r, uint32_t addr) {
    asm volatile("ldmatrix.sync.aligned.m8n8.x4.shared.b16 {%0,%1,%2,%3}, [%4];"
                 : "=r"(r[0]), "=r"(r[1]), "=r"(r[2]), "=r"(r[3]) : "r"(addr));
}
__device__ __forceinline__ void ldsm_x4_t(uint32_t* r, uint32_t addr) {
    asm volatile("ldmatrix.sync.aligned.m8n8.x4.trans.shared.b16 {%0,%1,%2,%3}, [%4];"
                 : "=r"(r[0]), "=r"(r[1]), "=r"(r[2]), "=r"(r[3]) : "r"(addr));
}

// ---------------------------------------------------------------------------
// Kernel 1: fused 1x1 convs as fp16 tensor-core GEMM (fp32 accumulate)
//   (mainloop unchanged from R12; epilogue now stores fp16 g_buf)
// ---------------------------------------------------------------------------
#define KC    32
#define ASPH  40
#define BSPH  264
#define ABUFH (128 * ASPH)
#define BBUFH (KC * BSPH)
#define CONV_SMEM_BYTES ((2 * ABUFH + 2 * BBUFH) * 2)   // 54272 B

__global__ __launch_bounds__(256, 1) void conv_kernel(
    const float* __restrict__ x,
    const float* __restrict__ qk_w,
    const float* __restrict__ v_w)
{
    extern __shared__ __half smh[];
    __half* Ah = smh;                 // [2][128][ASPH]
    __half* Bh = smh + 2 * ABUFH;     // [2][KC][BSPH]

    const int b  = blockIdx.z;
    const int m0 = blockIdx.y * 128;
    const int n0 = blockIdx.x * 256;

    const int tid  = threadIdx.x;
    const int lane = tid & 31;
    const int wid  = tid >> 5;
    const int wm   = (wid >> 2) * 64;
    const int wn   = (wid & 3) * 64;

    const int mA = tid & 127;
    const int kq = tid >> 7;
    const int am = m0 + mA;
    const float* wptr = (am < 512) ? (qk_w + (size_t)am * 256)
                                   : (v_w + (size_t)(am - 512) * 256);
    const int nIdx = (tid & 63) * 4;
    const int kr   = tid >> 6;
    const int nB   = n0 + nIdx;
    const float* xptr = x + (size_t)b * CIN * HW + nB;
    const bool nOK = (nB < HW);

    float acc[4][8][4];
#pragma unroll
    for (int mm = 0; mm < 4; ++mm)
#pragma unroll
        for (int nt = 0; nt < 8; ++nt)
#pragma unroll
            for (int r = 0; r < 4; ++r) acc[mm][nt][r] = 0.f;

    float4 avr[4], bvr[8];
    auto load_chunk = [&](int k0) {
#pragma unroll
        for (int q = 0; q < 4; ++q)
            avr[q] = *reinterpret_cast<const float4*>(wptr + k0 + kq * 16 + q * 4);
#pragma unroll
        for (int j = 0; j < 8; ++j) {
            if (nOK) bvr[j] = *reinterpret_cast<const float4*>(xptr + (size_t)(k0 + kr + 4 * j) * HW);
            else     bvr[j] = make_float4(0.f, 0.f, 0.f, 0.f);
        }
    };
    auto store_chunk = [&](int buf) {
        __half* Ab = Ah + buf * ABUFH + mA * ASPH;
#pragma unroll
        for (int q = 0; q < 4; ++q) {
            const int kk = kq * 16 + q * 4;
            uint2 t;
            t.x = pack_f16x2(avr[q].x, avr[q].y);
            t.y = pack_f16x2(avr[q].z, avr[q].w);
            *reinterpret_cast<uint2*>(Ab + kk) = t;
        }
        __half* Bb = Bh + buf * BBUFH + nIdx;
#pragma unroll
        for (int j = 0; j < 8; ++j) {
            const int kk = kr + 4 * j;
            uint2 t;
            t.x = pack_f16x2(bvr[j].x, bvr[j].y);
            t.y = pack_f16x2(bvr[j].z, bvr[j].w);
            *reinterpret_cast<uint2*>(Bb + kk * BSPH) = t;
        }
    };

    load_chunk(0);
    store_chunk(0);
    __syncthreads();

    int cur = 0;
    for (int k0 = 0; k0 < 256; k0 += KC) {
        const bool more = (k0 + KC < 256);
        if (more) load_chunk(k0 + KC);

        const __half* Ab = Ah + cur * ABUFH;
        const __half* Bb = Bh + cur * BBUFH;
#pragma unroll
        for (int ks = 0; ks < 2; ++ks) {
            uint32_t a[4][4];
#pragma unroll
            for (int mt = 0; mt < 4; ++mt) {
                const int row = wm + mt * 16 + (lane & 15);
                const int kh  = ks * 16 + (lane >> 4) * 8;
                ldsm_x4(a[mt], (uint32_t)__cvta_generic_to_shared(Ab + row * ASPH + kh));
            }
            uint32_t bf[8][2];
#pragma unroll
            for (int p = 0; p < 4; ++p) {
                const int r    = lane & 7;
                const int seg  = lane >> 3;
                const int krow = ks * 16 + (seg & 1) * 8 + r;
                const int col  = wn + p * 16 + (seg >> 1) * 8;
                uint32_t t[4];
                ldsm_x4_t(t, (uint32_t)__cvta_generic_to_shared(Bb + krow * BSPH + col));
                bf[2 * p][0]     = t[0];
                bf[2 * p][1]     = t[1];
                bf[2 * p + 1][0] = t[2];
                bf[2 * p + 1][1] = t[3];
            }
#pragma unroll
            for (int mt = 0; mt < 4; ++mt)
#pragma unroll
                for (int nt = 0; nt < 8; ++nt)
                    mma_f16(acc[mt][nt], a[mt], bf[nt]);
        }

        if (more) store_chunk(cur ^ 1);
        __syncthreads();
        cur ^= 1;
    }

    // ---- epilogue: relu (v rows), rn-to-fp16, scatter pixel-major ----
    const int g   = lane >> 2;
    const int tig = lane & 3;
    const bool isv = (m0 >= 512);
#pragma unroll
    for (int mm = 0; mm < 4; ++mm) {
#pragma unroll
        for (int nt = 0; nt < 8; ++nt) {
            const int ncol = n0 + wn + nt * 8 + 2 * tig;
            const int mrow = m0 + wm + mm * 16 + g;
            float v0 = acc[mm][nt][0];
            float v1 = acc[mm][nt][1];
            float v2 = acc[mm][nt][2];
            float v3 = acc[mm][nt][3];
            if (isv) {
                v0 = fmaxf(v0, 0.f); v1 = fmaxf(v1, 0.f);
                v2 = fmaxf(v2, 0.f); v3 = fmaxf(v3, 0.f);
            }
            if (ncol < HW) {
                __half* d0 = g_buf + ((size_t)b * HW + ncol) * OCH + mrow;
                d0[0] = __float2half_rn(v0);
                d0[8] = __float2half_rn(v2);
            }
            if (ncol + 1 < HW) {
                __half* d1 = g_buf + ((size_t)b * HW + ncol + 1) * OCH + mrow;
                d1[0] = __float2half_rn(v1);
                d1[8] = __float2half_rn(v3);
            }
        }
    }
}

// ---------------------------------------------------------------------------
// Kernel 2: fp16 tensor-core window attention, both partitions in one launch.
// Block = (win, h|part<<2, b), 128 threads = 4 warps, one m16 row-tile each.
// Token dim padded to 64 -> 4 k16 steps both stages. Q/P: A-op ldmatrix;
// K natural [n][k] layout IS the col-major B operand (non-trans ldmatrix);
// V [k][n] uses trans ldmatrix (conv-validated pattern).
// All smem half buffers stride 72 halfs = 144B (== 16 mod 128, LDSM clean).
// ---------------------------------------------------------------------------
#define HQS 72
#define SST 68
#define ATTN_SMEM_BYTES (4 * 64 * HQS * 2 + 64 * SST * 4 + NTOK * 4 + 16)

__global__ __launch_bounds__(128) void attn_kernel()
{
    extern __shared__ char smraw[];
    __half* s_q = reinterpret_cast<__half*>(smraw);
    __half* s_k = s_q + 64 * HQS;
    __half* s_v = s_k + 64 * HQS;
    __half* s_P = s_v + 64 * HQS;
    float*  s_S = reinterpret_cast<float*>(s_P + 64 * HQS);   // [64][SST]
    int*    s_p = reinterpret_cast<int*>(s_S + 64 * SST);

    const int b    = blockIdx.z;
    const int h    = blockIdx.y & 3;
    const int part = blockIdx.y >> 2;
    const int win  = blockIdx.x;
    const int j1   = win >> 3;
    const int j2   = win & 7;
    const int tid  = threadIdx.x;
    const int lane = tid & 31;
    const int wid  = tid >> 5;
    const int g    = lane >> 2;
    const int tig  = lane & 3;
    const int wr   = wid * 16;

    if (tid < NTOK) {
        int h1 = tid / 7, w1 = tid - h1 * 7;
        int hh, ww;
        if (part == 0) { hh = h1 * 8 + j1; ww = w1 * 8 + j2; }   // remote
        else           { hh = j1 * 7 + h1; ww = j2 * 7 + w1; }   // close
        s_p[tid] = hh * WIMG + ww;
    }
    // zero V pad rows 49..63 (multiplied by explicit-zero P pad cols; must be finite)
    {
        uint32_t* vz = reinterpret_cast<uint32_t*>(s_v + NTOK * HQS);
        for (int i = tid; i < 15 * HQS / 2; i += 128) vz[i] = 0;
    }
    __syncthreads();

    // ---- stage q,k,v via cp.async: 49 pixels x 3 segs x 8 chunks of 16B ----
    {
        const __half* base = g_buf + (size_t)b * HW * OCH + h * 64;
        for (int idx = tid; idx < NTOK * 24; idx += 128) {
            const int pix = idx / 24;
            const int r   = idx - pix * 24;
            const int seg = r >> 3;          // 0=q,1=k,2=v
            const int ch  = r & 7;
            const __half* src = base + (size_t)s_p[pix] * OCH + seg * 256 + ch * 8;
            __half* dsth = (seg == 0 ? s_q : seg == 1 ? s_k : s_v) + pix * HQS + ch * 8;
            uint32_t dsta = (uint32_t)__cvta_generic_to_shared(dsth);
            asm volatile("cp.async.ca.shared.global [%0], [%1], 16;\n"
                         :: "r"(dsta), "l"(src));
        }
        asm volatile("cp.async.commit_group;\n");
        asm volatile("cp.async.wait_group 0;\n" ::: "memory");
    }
    __syncthreads();

    // ---- S = Q K^T * scale : 4 k16 steps x 8 n8-tiles per warp ----
    {
        float cS[8][4];
#pragma unroll
        for (int nt = 0; nt < 8; ++nt)
#pragma unroll
            for (int r = 0; r < 4; ++r) cS[nt][r] = 0.f;

#pragma unroll
        for (int ks = 0; ks < 4; ++ks) {
            uint32_t a[4];
            ldsm_x4(a, (uint32_t)__cvta_generic_to_shared(
                s_q + (wr + (lane & 15)) * HQS + ks * 16 + (lane >> 4) * 8));
            const int r  = lane & 7;
            const int s2 = lane >> 3;
#pragma unroll
            for (int ng = 0; ng < 4; ++ng) {
                uint32_t t[4];
                ldsm_x4(t, (uint32_t)__cvta_generic_to_shared(
                    s_k + (ng * 16 + (s2 >> 1) * 8 + r) * HQS + ks * 16 + (s2 & 1) * 8));
                mma_f16(cS[2 * ng],     a, t);       // {t0,t1}
                mma_f16(cS[2 * ng + 1], a, t + 2);   // {t2,t3}
            }
        }
#pragma unroll
        for (int nt = 0; nt < 8; ++nt) {
            float* S0 = s_S + (wr + g) * SST + nt * 8 + 2 * tig;
            float* S1 = s_S + (wr + g + 8) * SST + nt * 8 + 2 * tig;
            S0[0] = cS[nt][0] * 0.125f;
            S0[1] = cS[nt][1] * 0.125f;
            S1[0] = cS[nt][2] * 0.125f;
            S1[1] = cS[nt][3] * 0.125f;
        }
    }
    __syncthreads();

    // ---- softmax rows 0..48; write probs fp16; zero pad cols 49..63 ----
    for (int row = wid; row < NTOK; row += 4) {
        float* Srow = s_S + row * SST;
        __half* Prow = s_P + row * HQS;
        float v0 = Srow[lane];
        float v1 = (lane < 17) ? Srow[lane + 32] : -3.0e38f;
        float m = fmaxf(v0, v1);
#pragma unroll
        for (int off = 16; off; off >>= 1) m = fmaxf(m, __shfl_xor_sync(0xffffffffu, m, off));
        float e0 = __expf(v0 - m);
        float e1 = (lane < 17) ? __expf(v1 - m) : 0.f;
        float s = e0 + e1;
#pragma unroll
        for (int off = 16; off; off >>= 1) s += __shfl_xor_sync(0xffffffffu, s, off);
        const float inv = 1.f / s;
        Prow[lane]      = __float2half_rn(e0 * inv);
        Prow[lane + 32] = (lane < 17) ? __float2half_rn(e1 * inv) : __float2half_rn(0.f);
    }
    __syncthreads();

    // ---- O = P V : 4 k16 steps x 8 d8-tiles per warp ----
    {
        float cO[8][4];
#pragma unroll
        for (int nt = 0; nt < 8; ++nt)
#pragma unroll
            for (int r = 0; r < 4; ++r) cO[nt][r] = 0.f;

#pragma unroll
        for (int ks = 0; ks < 4; ++ks) {
            uint32_t a[4];
            ldsm_x4(a, (uint32_t)__cvta_generic_to_shared(
                s_P + (wr + (lane & 15)) * HQS + ks * 16 + (lane >> 4) * 8));
            const int r  = lane & 7;
            const int s2 = lane >> 3;
#pragma unroll
            for (int p = 0; p < 4; ++p) {
                uint32_t t[4];
                ldsm_x4_t(t, (uint32_t)__cvta_generic_to_shared(
                    s_v + (ks * 16 + (s2 & 1) * 8 + r) * HQS + p * 16 + (s2 >> 1) * 8));
                mma_f16(cO[2 * p],     a, t);
                mma_f16(cO[2 * p + 1], a, t + 2);
            }
        }

        __half* obuf = (part == 0) ? o_r : o_c;
        const int r0 = wr + g;
        const int r1 = r0 + 8;
#pragma unroll
        for (int nt = 0; nt < 8; ++nt) {
            const int d = h * 64 + nt * 8 + 2 * tig;
            if (r0 < NTOK) {
                *reinterpret_cast<uint32_t*>(&obuf[((size_t)b * HW + s_p[r0]) * 256 + d]) =
                    pack_f16x2(cO[nt][0], cO[nt][1]);
            }
            if (r1 < NTOK) {
                *reinterpret_cast<uint32_t*>(&obuf[((size_t)b * HW + s_p[r1]) * 256 + d]) =
                    pack_f16x2(cO[nt][2], cO[nt][3]);
            }
        }
    }
}

// ---------------------------------------------------------------------------
// Kernel 3: merge + transpose: out[b][c][p] = o_r[b][p][c] + o_c[b][p][c]
// ---------------------------------------------------------------------------
__global__ __launch_bounds__(256) void merge_kernel(float* __restrict__ out)
{
    __shared__ float tile[32][33];
    const int b  = blockIdx.z;
    const int c0 = blockIdx.y * 32;
    const int p0 = blockIdx.x * 32;
    const int tx = threadIdx.x & 31;
    const int ty = threadIdx.x >> 5;

#pragma unroll
    for (int i = 0; i < 4; ++i) {
        const int p = p0 + ty + i * 8;
        const size_t off = ((size_t)b * HW + p) * 256 + c0 + tx;
        tile[ty + i * 8][tx] = __half2float(o_r[off]) + __half2float(o_c[off]);
    }
    __syncthreads();
#pragma unroll
    for (int i = 0; i < 4; ++i) {
        const int c = c0 + ty + i * 8;
        out[((size_t)b * 256 + c) * HW + p0 + tx] = tile[tx][ty + i * 8];
    }
}

// ---------------------------------------------------------------------------
extern "C" void kernel_launch(void* const* d_in, const int* in_sizes, int n_in,
                              void* d_out, int out_size)
{
    const float* x    = (const float*)d_in[0];
    const float* qk_w = (const float*)d_in[1];
    const float* v_w  = (const float*)d_in[2];
    float* out = (float*)d_out;

    cudaFuncSetAttribute(conv_kernel, cudaFuncAttributeMaxDynamicSharedMemorySize, CONV_SMEM_BYTES);
    conv_kernel<<<dim3(13, 6, 32), 256, CONV_SMEM_BYTES>>>(x, qk_w, v_w);

    cudaFuncSetAttribute(attn_kernel, cudaFuncAttributeMaxDynamicSharedMemorySize, ATTN_SMEM_BYTES);
    attn_kernel<<<dim3(64, 8, 32), 128, ATTN_SMEM_BYTES>>>();

    merge_kernel<<<dim3(98, 8, 32), 256>>>(out);
}

// round 16
// speedup vs baseline: 1.9939x; 1.2529x over previous
#include <cuda_runtime.h>
#include <cuda_fp16.h>
#include <cstdint>
#include <cstddef>

#define BATCH 32
#define CIN   256
#define HW    3136
#define WIMG  56
#define NTOK  49
#define OCH   768

// Scratch: conv output (fp16), pixel-major [b][p][o] ; 0..511 qk, 512..767 v(relu)
__device__ __half g_buf[(size_t)BATCH * HW * OCH];
// Attention output scratch (fp16), pixel-major [b][p][256], one per partition
__device__ __half o_r[(size_t)BATCH * HW * 256];
__device__ __half o_c[(size_t)BATCH * HW * 256];

__device__ __forceinline__ uint32_t pack_f16x2(float lo, float hi) {
    uint32_t d;
    asm("cvt.rn.f16x2.f32 %0, %1, %2;" : "=r"(d) : "f"(hi), "f"(lo));
    return d;
}

__device__ __forceinline__ void mma_f16(float* c, const uint32_t* a, const uint32_t* b) {
    asm volatile(
        "mma.sync.aligned.m16n8k16.row.col.f32.f16.f16.f32 "
        "{%0,%1,%2,%3}, {%4,%5,%6,%7}, {%8,%9}, {%0,%1,%2,%3};"
        : "+f"(c[0]), "+f"(c[1]), "+f"(c[2]), "+f"(c[3])
        : "r"(a[0]), "r"(a[1]), "r"(a[2]), "r"(a[3]), "r"(b[0]), "r"(b[1]));
}

__device__ __forceinline__ void ldsm_x4(uint32_t* r, uint32_t addr) {
    asm volatile("ldmatrix.sync.aligned.m8n8.x4.shared.b16 {%0,%1,%2,%3}, [%4];"
                 : "=r"(r[0]), "=r"(r[1]), "=r"(r[2]), "=r"(r[3]) : "r"(addr));
}
__device__ __forceinline__ void ldsm_x4_t(uint32_t* r, uint32_t addr) {
    asm volatile("ldmatrix.sync.aligned.m8n8.x4.trans.shared.b16 {%0,%1,%2,%3}, [%4];"
                 : "=r"(r[0]), "=r"(r[1]), "=r"(r[2]), "=r"(r[3]) : "r"(addr));
}

// ---------------------------------------------------------------------------
// Kernel 1: fused 1x1 convs as fp16 tensor-core GEMM (fp32 accumulate)
// Mainloop unchanged from R14. Epilogue now stages C through smem so the
// fp16 g_buf stores are fully coalesced (128B contiguous chunks per pixel).
// ---------------------------------------------------------------------------
#define KC    32
#define ASPH  40
#define BSPH  264
#define ABUFH (128 * ASPH)
#define BBUFH (KC * BSPH)
#define CONV_SMEM_BYTES ((2 * ABUFH + 2 * BBUFH) * 2)   // 54272 B

__global__ __launch_bounds__(256, 1) void conv_kernel(
    const float* __restrict__ x,
    const float* __restrict__ qk_w,
    const float* __restrict__ v_w)
{
    extern __shared__ __half smh[];
    __half* Ah = smh;                 // [2][128][ASPH]
    __half* Bh = smh + 2 * ABUFH;     // [2][KC][BSPH]

    const int b  = blockIdx.z;
    const int m0 = blockIdx.y * 128;
    const int n0 = blockIdx.x * 256;

    const int tid  = threadIdx.x;
    const int lane = tid & 31;
    const int wid  = tid >> 5;
    const int wm   = (wid >> 2) * 64;
    const int wn   = (wid & 3) * 64;

    const int mA = tid & 127;
    const int kq = tid >> 7;
    const int am = m0 + mA;
    const float* wptr = (am < 512) ? (qk_w + (size_t)am * 256)
                                   : (v_w + (size_t)(am - 512) * 256);
    const int nIdx = (tid & 63) * 4;
    const int kr   = tid >> 6;
    const int nB   = n0 + nIdx;
    const float* xptr = x + (size_t)b * CIN * HW + nB;
    const bool nOK = (nB < HW);

    float acc[4][8][4];
#pragma unroll
    for (int mm = 0; mm < 4; ++mm)
#pragma unroll
        for (int nt = 0; nt < 8; ++nt)
#pragma unroll
            for (int r = 0; r < 4; ++r) acc[mm][nt][r] = 0.f;

    float4 avr[4], bvr[8];
    auto load_chunk = [&](int k0) {
#pragma unroll
        for (int q = 0; q < 4; ++q)
            avr[q] = *reinterpret_cast<const float4*>(wptr + k0 + kq * 16 + q * 4);
#pragma unroll
        for (int j = 0; j < 8; ++j) {
            if (nOK) bvr[j] = *reinterpret_cast<const float4*>(xptr + (size_t)(k0 + kr + 4 * j) * HW);
            else     bvr[j] = make_float4(0.f, 0.f, 0.f, 0.f);
        }
    };
    auto store_chunk = [&](int buf) {
        __half* Ab = Ah + buf * ABUFH + mA * ASPH;
#pragma unroll
        for (int q = 0; q < 4; ++q) {
            const int kk = kq * 16 + q * 4;
            uint2 t;
            t.x = pack_f16x2(avr[q].x, avr[q].y);
            t.y = pack_f16x2(avr[q].z, avr[q].w);
            *reinterpret_cast<uint2*>(Ab + kk) = t;
        }
        __half* Bb = Bh + buf * BBUFH + nIdx;
#pragma unroll
        for (int j = 0; j < 8; ++j) {
            const int kk = kr + 4 * j;
            uint2 t;
            t.x = pack_f16x2(bvr[j].x, bvr[j].y);
            t.y = pack_f16x2(bvr[j].z, bvr[j].w);
            *reinterpret_cast<uint2*>(Bb + kk * BSPH) = t;
        }
    };

    load_chunk(0);
    store_chunk(0);
    __syncthreads();

    int cur = 0;
    for (int k0 = 0; k0 < 256; k0 += KC) {
        const bool more = (k0 + KC < 256);
        if (more) load_chunk(k0 + KC);

        const __half* Ab = Ah + cur * ABUFH;
        const __half* Bb = Bh + cur * BBUFH;
#pragma unroll
        for (int ks = 0; ks < 2; ++ks) {
            uint32_t a[4][4];
#pragma unroll
            for (int mt = 0; mt < 4; ++mt) {
                const int row = wm + mt * 16 + (lane & 15);
                const int kh  = ks * 16 + (lane >> 4) * 8;
                ldsm_x4(a[mt], (uint32_t)__cvta_generic_to_shared(Ab + row * ASPH + kh));
            }
            uint32_t bf[8][2];
#pragma unroll
            for (int p = 0; p < 4; ++p) {
                const int r    = lane & 7;
                const int seg  = lane >> 3;
                const int krow = ks * 16 + (seg & 1) * 8 + r;
                const int col  = wn + p * 16 + (seg >> 1) * 8;
                uint32_t t[4];
                ldsm_x4_t(t, (uint32_t)__cvta_generic_to_shared(Bb + krow * BSPH + col));
                bf[2 * p][0]     = t[0];
                bf[2 * p][1]     = t[1];
                bf[2 * p + 1][0] = t[2];
                bf[2 * p + 1][1] = t[3];
            }
#pragma unroll
            for (int mt = 0; mt < 4; ++mt)
#pragma unroll
                for (int nt = 0; nt < 8; ++nt)
                    mma_f16(acc[mt][nt], a[mt], bf[nt]);
        }

        if (more) store_chunk(cur ^ 1);
        __syncthreads();
        cur ^= 1;
    }

    // ---- epilogue: stage C tile in smem, then coalesced fp16 g_buf stores ----
    // Cs layout: [128 local pixels][136 halfs] (stride 136 spreads banks).
    {
        __half* Cs = smh;
        const int g   = lane >> 2;
        const int tig = lane & 3;
        const bool isv = (m0 >= 512);
        const int pp_st = tid & 127;   // STG: pixel
        const int hf    = tid >> 7;    // STG: 64-half chunk index

#pragma unroll
        for (int r = 0; r < 2; ++r) {
            if (((wid & 3) >> 1) == r) {
                const int pl = (wid & 1) * 64;
#pragma unroll
                for (int mm = 0; mm < 4; ++mm) {
#pragma unroll
                    for (int nt = 0; nt < 8; ++nt) {
                        const int pp = pl + nt * 8 + 2 * tig;
                        const int ch = wm + mm * 16 + g;
                        float v0 = acc[mm][nt][0];
                        float v1 = acc[mm][nt][1];
                        float v2 = acc[mm][nt][2];
                        float v3 = acc[mm][nt][3];
                        if (isv) {
                            v0 = fmaxf(v0, 0.f); v1 = fmaxf(v1, 0.f);
                            v2 = fmaxf(v2, 0.f); v3 = fmaxf(v3, 0.f);
                        }
                        Cs[pp * 136 + ch]           = __float2half_rn(v0);
                        Cs[pp * 136 + ch + 8]       = __float2half_rn(v2);
                        Cs[(pp + 1) * 136 + ch]     = __float2half_rn(v1);
                        Cs[(pp + 1) * 136 + ch + 8] = __float2half_rn(v3);
                    }
                }
            }
            __syncthreads();
            const int ncol = n0 + r * 128 + pp_st;
            if (ncol < HW) {
                const __half* src = Cs + pp_st * 136 + hf * 64;
                __half* dst = g_buf + ((size_t)b * HW + ncol) * OCH + m0 + hf * 64;
#pragma unroll
                for (int i = 0; i < 8; ++i)
                    *reinterpret_cast<uint4*>(dst + i * 8) =
                        *reinterpret_cast<const uint4*>(src + i * 8);
            }
            __syncthreads();
        }
    }
}

// ---------------------------------------------------------------------------
// Kernel 2: fp16 tensor-core window attention, register-resident softmax.
// Block = (win, h|part<<2, b), 128 threads = 4 warps, one m16 row-tile each.
// S stays in mma accumulators: C-fragment (row=g, col=2tig+{0,1}) == A-fragment
// layout for the PV mma, so softmax happens in registers with 2 shfl_xor per
// reduction and probs are packed straight into PV A-operands. No s_S/s_P,
// only 2 barriers, smem 28KB -> 8 CTAs/SM.
// ---------------------------------------------------------------------------
#define HQS 72
#define ATTN_SMEM_BYTES (3 * 64 * HQS * 2 + NTOK * 4 + 16)

__global__ __launch_bounds__(128) void attn_kernel()
{
    extern __shared__ char smraw[];
    __half* s_q = reinterpret_cast<__half*>(smraw);
    __half* s_k = s_q + 64 * HQS;
    __half* s_v = s_k + 64 * HQS;
    int*    s_p = reinterpret_cast<int*>(s_v + 64 * HQS);

    const int b    = blockIdx.z;
    const int h    = blockIdx.y & 3;
    const int part = blockIdx.y >> 2;
    const int win  = blockIdx.x;
    const int j1   = win >> 3;
    const int j2   = win & 7;
    const int tid  = threadIdx.x;
    const int lane = tid & 31;
    const int wid  = tid >> 5;
    const int g    = lane >> 2;
    const int tig  = lane & 3;
    const int wr   = wid * 16;

    if (tid < NTOK) {
        int h1 = tid / 7, w1 = tid - h1 * 7;
        int hh, ww;
        if (part == 0) { hh = h1 * 8 + j1; ww = w1 * 8 + j2; }   // remote
        else           { hh = j1 * 7 + h1; ww = j2 * 7 + w1; }   // close
        s_p[tid] = hh * WIMG + ww;
    }
    // zero V pad rows 49..63 (multiplied by exact-zero P pad cols; must be finite)
    {
        uint32_t* vz = reinterpret_cast<uint32_t*>(s_v + NTOK * HQS);
        for (int i = tid; i < 15 * HQS / 2; i += 128) vz[i] = 0;
    }
    __syncthreads();

    // ---- stage q,k,v via cp.async: 49 pixels x 3 segs x 8 chunks of 16B ----
    {
        const __half* base = g_buf + (size_t)b * HW * OCH + h * 64;
        for (int idx = tid; idx < NTOK * 24; idx += 128) {
            const int pix = idx / 24;
            const int r   = idx - pix * 24;
            const int seg = r >> 3;          // 0=q,1=k,2=v
            const int ch  = r & 7;
            const __half* src = base + (size_t)s_p[pix] * OCH + seg * 256 + ch * 8;
            __half* dsth = (seg == 0 ? s_q : seg == 1 ? s_k : s_v) + pix * HQS + ch * 8;
            uint32_t dsta = (uint32_t)__cvta_generic_to_shared(dsth);
            asm volatile("cp.async.ca.shared.global [%0], [%1], 16;\n"
                         :: "r"(dsta), "l"(src));
        }
        asm volatile("cp.async.commit_group;\n");
        asm volatile("cp.async.wait_group 0;\n" ::: "memory");
    }
    __syncthreads();

    // ---- S = Q K^T : 4 k16 steps x 8 n8-tiles per warp (accumulate in regs) ----
    float cS[8][4];
#pragma unroll
    for (int nt = 0; nt < 8; ++nt)
#pragma unroll
        for (int r = 0; r < 4; ++r) cS[nt][r] = 0.f;

#pragma unroll
    for (int ks = 0; ks < 4; ++ks) {
        uint32_t a[4];
        ldsm_x4(a, (uint32_t)__cvta_generic_to_shared(
            s_q + (wr + (lane & 15)) * HQS + ks * 16 + (lane >> 4) * 8));
        const int r  = lane & 7;
        const int s2 = lane >> 3;
#pragma unroll
        for (int ng = 0; ng < 4; ++ng) {
            uint32_t t[4];
            ldsm_x4(t, (uint32_t)__cvta_generic_to_shared(
                s_k + (ng * 16 + (s2 >> 1) * 8 + r) * HQS + ks * 16 + (s2 & 1) * 8));
            mma_f16(cS[2 * ng],     a, t);
            mma_f16(cS[2 * ng + 1], a, t + 2);
        }
    }

    // ---- in-register softmax over valid cols 0..48 ----
    // rows: r0 = wr+g (cS[nt][0..1]), r1 = wr+g+8 (cS[nt][2..3]);
    // col of cS[nt][c&1] = nt*8 + 2*tig + (c&1). Reduce across tig via shfl_xor 1,2.
#pragma unroll
    for (int nt = 0; nt < 8; ++nt) {
        const int c0 = nt * 8 + 2 * tig;
        const bool ok0 = (c0 <= 48);
        const bool ok1 = (c0 + 1 <= 48);
        cS[nt][0] = ok0 ? cS[nt][0] * 0.125f : -1e30f;
        cS[nt][1] = ok1 ? cS[nt][1] * 0.125f : -1e30f;
        cS[nt][2] = ok0 ? cS[nt][2] * 0.125f : -1e30f;
        cS[nt][3] = ok1 ? cS[nt][3] * 0.125f : -1e30f;
    }
    float mx0 = -1e30f, mx1 = -1e30f;
#pragma unroll
    for (int nt = 0; nt < 8; ++nt) {
        mx0 = fmaxf(mx0, fmaxf(cS[nt][0], cS[nt][1]));
        mx1 = fmaxf(mx1, fmaxf(cS[nt][2], cS[nt][3]));
    }
    mx0 = fmaxf(mx0, __shfl_xor_sync(0xffffffffu, mx0, 1));
    mx0 = fmaxf(mx0, __shfl_xor_sync(0xffffffffu, mx0, 2));
    mx1 = fmaxf(mx1, __shfl_xor_sync(0xffffffffu, mx1, 1));
    mx1 = fmaxf(mx1, __shfl_xor_sync(0xffffffffu, mx1, 2));
    float s0 = 0.f, s1 = 0.f;
#pragma unroll
    for (int nt = 0; nt < 8; ++nt) {
        cS[nt][0] = __expf(cS[nt][0] - mx0);
        cS[nt][1] = __expf(cS[nt][1] - mx0);
        cS[nt][2] = __expf(cS[nt][2] - mx1);
        cS[nt][3] = __expf(cS[nt][3] - mx1);
        s0 += cS[nt][0] + cS[nt][1];
        s1 += cS[nt][2] + cS[nt][3];
    }
    s0 += __shfl_xor_sync(0xffffffffu, s0, 1);
    s0 += __shfl_xor_sync(0xffffffffu, s0, 2);
    s1 += __shfl_xor_sync(0xffffffffu, s1, 1);
    s1 += __shfl_xor_sync(0xffffffffu, s1, 2);
    const float i0 = 1.f / s0;
    const float i1 = 1.f / s1;

    // pack normalized probs directly into PV A-fragments (C layout == A layout)
    uint32_t aP[4][4];
#pragma unroll
    for (int ks = 0; ks < 4; ++ks) {
        aP[ks][0] = pack_f16x2(cS[2 * ks][0] * i0,     cS[2 * ks][1] * i0);
        aP[ks][1] = pack_f16x2(cS[2 * ks][2] * i1,     cS[2 * ks][3] * i1);
        aP[ks][2] = pack_f16x2(cS[2 * ks + 1][0] * i0, cS[2 * ks + 1][1] * i0);
        aP[ks][3] = pack_f16x2(cS[2 * ks + 1][2] * i1, cS[2 * ks + 1][3] * i1);
    }

    // ---- O = P V : 4 k16 steps x 8 d8-tiles per warp ----
    {
        float cO[8][4];
#pragma unroll
        for (int nt = 0; nt < 8; ++nt)
#pragma unroll
            for (int r = 0; r < 4; ++r) cO[nt][r] = 0.f;

#pragma unroll
        for (int ks = 0; ks < 4; ++ks) {
            const int r  = lane & 7;
            const int s2 = lane >> 3;
#pragma unroll
            for (int p = 0; p < 4; ++p) {
                uint32_t t[4];
                ldsm_x4_t(t, (uint32_t)__cvta_generic_to_shared(
                    s_v + (ks * 16 + (s2 & 1) * 8 + r) * HQS + p * 16 + (s2 >> 1) * 8));
                mma_f16(cO[2 * p],     aP[ks], t);
                mma_f16(cO[2 * p + 1], aP[ks], t + 2);
            }
        }

        __half* obuf = (part == 0) ? o_r : o_c;
        const int r0 = wr + g;
        const int r1 = r0 + 8;
#pragma unroll
        for (int nt = 0; nt < 8; ++nt) {
            const int d = h * 64 + nt * 8 + 2 * tig;
            if (r0 < NTOK) {
                *reinterpret_cast<uint32_t*>(&obuf[((size_t)b * HW + s_p[r0]) * 256 + d]) =
                    pack_f16x2(cO[nt][0], cO[nt][1]);
            }
            if (r1 < NTOK) {
                *reinterpret_cast<uint32_t*>(&obuf[((size_t)b * HW + s_p[r1]) * 256 + d]) =
                    pack_f16x2(cO[nt][2], cO[nt][3]);
            }
        }
    }
}

// ---------------------------------------------------------------------------
// Kernel 3: merge + transpose: out[b][c][p] = o_r[b][p][c] + o_c[b][p][c]
// ---------------------------------------------------------------------------
__global__ __launch_bounds__(256) void merge_kernel(float* __restrict__ out)
{
    __shared__ float tile[32][33];
    const int b  = blockIdx.z;
    const int c0 = blockIdx.y * 32;
    const int p0 = blockIdx.x * 32;
    const int tx = threadIdx.x & 31;
    const int ty = threadIdx.x >> 5;

#pragma unroll
    for (int i = 0; i < 4; ++i) {
        const int p = p0 + ty + i * 8;
        const size_t off = ((size_t)b * HW + p) * 256 + c0 + tx;
        tile[ty + i * 8][tx] = __half2float(o_r[off]) + __half2float(o_c[off]);
    }
    __syncthreads();
#pragma unroll
    for (int i = 0; i < 4; ++i) {
        const int c = c0 + ty + i * 8;
        out[((size_t)b * 256 + c) * HW + p0 + tx] = tile[tx][ty + i * 8];
    }
}

// ---------------------------------------------------------------------------
extern "C" void kernel_launch(void* const* d_in, const int* in_sizes, int n_in,
                              void* d_out, int out_size)
{
    const float* x    = (const float*)d_in[0];
    const float* qk_w = (const float*)d_in[1];
    const float* v_w  = (const float*)d_in[2];
    float* out = (float*)d_out;

    cudaFuncSetAttribute(conv_kernel, cudaFuncAttributeMaxDynamicSharedMemorySize, CONV_SMEM_BYTES);
    conv_kernel<<<dim3(13, 6, 32), 256, CONV_SMEM_BYTES>>>(x, qk_w, v_w);

    cudaFuncSetAttribute(attn_kernel, cudaFuncAttributeMaxDynamicSharedMemorySize, ATTN_SMEM_BYTES);
    attn_kernel<<<dim3(64, 8, 32), 128, ATTN_SMEM_BYTES>>>();

    merge_kernel<<<dim3(98, 8, 32), 256>>>(out);
}

// round 17
// speedup vs baseline: 2.3335x; 1.1703x over previous
#include <cuda_runtime.h>
#include <cuda_fp16.h>
#include <cstdint>
#include <cstddef>

#define BATCH 32
#define CIN   256
#define HW    3136
#define WIMG  56
#define NTOK  49
#define OCH   768

// fp16 packed inputs (filled once per launch by pack kernels)
__device__ __half x_h[(size_t)BATCH * CIN * HW];     // [b][c][p]
__device__ __half w_h[OCH * CIN];                    // [m][k]: 0..511 qk_w, 512..767 v_w
// Scratch: conv output (fp16), pixel-major [b][p][o] ; 0..511 qk, 512..767 v(relu)
__device__ __half g_buf[(size_t)BATCH * HW * OCH];
// Attention output scratch (fp16), pixel-major [b][p][256], one per partition
__device__ __half o_r[(size_t)BATCH * HW * 256];
__device__ __half o_c[(size_t)BATCH * HW * 256];

__device__ __forceinline__ uint32_t pack_f16x2(float lo, float hi) {
    uint32_t d;
    asm("cvt.rn.f16x2.f32 %0, %1, %2;" : "=r"(d) : "f"(hi), "f"(lo));
    return d;
}

__device__ __forceinline__ void mma_f16(float* c, const uint32_t* a, const uint32_t* b) {
    asm volatile(
        "mma.sync.aligned.m16n8k16.row.col.f32.f16.f16.f32 "
        "{%0,%1,%2,%3}, {%4,%5,%6,%7}, {%8,%9}, {%0,%1,%2,%3};"
        : "+f"(c[0]), "+f"(c[1]), "+f"(c[2]), "+f"(c[3])
        : "r"(a[0]), "r"(a[1]), "r"(a[2]), "r"(a[3]), "r"(b[0]), "r"(b[1]));
}

__device__ __forceinline__ void ldsm_x4(uint32_t* r, uint32_t addr) {
    asm volatile("ldmatrix.sync.aligned.m8n8.x4.shared.b16 {%0,%1,%2,%3}, [%4];"
                 : "=r"(r[0]), "=r"(r[1]), "=r"(r[2]), "=r"(r[3]) : "r"(addr));
}
__device__ __forceinline__ void ldsm_x4_t(uint32_t* r, uint32_t addr) {
    asm volatile("ldmatrix.sync.aligned.m8n8.x4.trans.shared.b16 {%0,%1,%2,%3}, [%4];"
                 : "=r"(r[0]), "=r"(r[1]), "=r"(r[2]), "=r"(r[3]) : "r"(addr));
}

__device__ __forceinline__ void cp16(void* dst, const void* src) {
    uint32_t d = (uint32_t)__cvta_generic_to_shared(dst);
    asm volatile("cp.async.ca.shared.global [%0], [%1], 16;\n" :: "r"(d), "l"(src));
}
__device__ __forceinline__ void cp16z(void* dst, const void* src, int sz) {
    uint32_t d = (uint32_t)__cvta_generic_to_shared(dst);
    asm volatile("cp.async.ca.shared.global [%0], [%1], 16, %2;\n" :: "r"(d), "l"(src), "r"(sz));
}

// ---------------------------------------------------------------------------
// Kernel 0a/0b: pack fp32 inputs to fp16 (one-time per launch)
// ---------------------------------------------------------------------------
__global__ __launch_bounds__(256) void pack_x_kernel(const float* __restrict__ x)
{
    const size_t i = ((size_t)blockIdx.x * 256 + threadIdx.x) * 8;
    float4 v0 = *reinterpret_cast<const float4*>(x + i);
    float4 v1 = *reinterpret_cast<const float4*>(x + i + 4);
    uint4 t;
    t.x = pack_f16x2(v0.x, v0.y);
    t.y = pack_f16x2(v0.z, v0.w);
    t.z = pack_f16x2(v1.x, v1.y);
    t.w = pack_f16x2(v1.z, v1.w);
    *reinterpret_cast<uint4*>(x_h + i) = t;
}

__global__ __launch_bounds__(256) void pack_w_kernel(const float* __restrict__ qk_w,
                                                     const float* __restrict__ v_w)
{
    const int i = (blockIdx.x * 256 + threadIdx.x) * 8;
    const float* src = (i < 512 * 256) ? qk_w + i : v_w + (i - 512 * 256);
    float4 v0 = *reinterpret_cast<const float4*>(src);
    float4 v1 = *reinterpret_cast<const float4*>(src + 4);
    uint4 t;
    t.x = pack_f16x2(v0.x, v0.y);
    t.y = pack_f16x2(v0.z, v0.w);
    t.z = pack_f16x2(v1.x, v1.y);
    t.w = pack_f16x2(v1.z, v1.w);
    *reinterpret_cast<uint4*>(w_h + i) = t;
}

// ---------------------------------------------------------------------------
// Kernel 1: fused 1x1 convs as fp16 tensor-core GEMM (fp32 accumulate)
//   C[768,3136] = W[768,256] @ X[256,3136]  per batch
// Block tile 128(m) x 256(n), warp tile 64x64 (8 warps, 2m x 4n).
// 3-stage cp.async pipeline on pre-packed fp16 inputs: issue chunk i+3,
// wait_group 2 (2 chunks always in flight), no register staging, no cvt.
// A smem [m=128][40 halfs], B smem [k=32][264 halfs] — LDSM-clean strides.
// ---------------------------------------------------------------------------
#define KC    32
#define ASPH  40
#define BSPH  264
#define ABUFH (128 * ASPH)          // 5120 halfs
#define BBUFH (KC * BSPH)           // 8448 halfs
#define NSTG  3
#define CONV_SMEM_BYTES (NSTG * (ABUFH + BBUFH) * 2)   // 81408 B

__global__ __launch_bounds__(256, 1) void conv_kernel()
{
    extern __shared__ __half smh[];
    __half* Ah = smh;                     // [NSTG][128][ASPH]
    __half* Bh = smh + NSTG * ABUFH;      // [NSTG][KC][BSPH]

    const int b  = blockIdx.z;
    const int m0 = blockIdx.y * 128;
    const int n0 = blockIdx.x * 256;

    const int tid  = threadIdx.x;
    const int lane = tid & 31;
    const int wid  = tid >> 5;
    const int wm   = (wid >> 2) * 64;
    const int wn   = (wid & 3) * 64;

    // A loader: row mA, 2 chunks of 8 halfs at k = kq*16 + {0,8}
    const int mA = tid & 127;
    const int kq = tid >> 7;              // 0..1
    const __half* wsrc = w_h + (m0 + mA) * 256 + kq * 16;
    // B loader: n chunk n8 (8 halfs), k rows kr + 8j (j=0..3)
    const int n8 = tid & 31;              // 0..31
    const int kr = tid >> 5;              // 0..7
    const int nB = n0 + n8 * 8;
    const __half* xsrc = x_h + (size_t)b * CIN * HW + nB;
    const int bsz = (nB < HW) ? 16 : 0;   // HW % 8 == 0: all-or-nothing per chunk

    float acc[4][8][4];
#pragma unroll
    for (int mm = 0; mm < 4; ++mm)
#pragma unroll
        for (int nt = 0; nt < 8; ++nt)
#pragma unroll
            for (int r = 0; r < 4; ++r) acc[mm][nt][r] = 0.f;

    auto issue_chunk = [&](int k0, int s) {
        __half* Ab = Ah + s * ABUFH + mA * ASPH + kq * 16;
        cp16(Ab,     wsrc + k0);
        cp16(Ab + 8, wsrc + k0 + 8);
        __half* Bb = Bh + s * BBUFH + n8 * 8;
#pragma unroll
        for (int j = 0; j < 4; ++j) {
            const int kk = kr + 8 * j;
            cp16z(Bb + kk * BSPH, xsrc + (size_t)(k0 + kk) * HW, bsz);
        }
        asm volatile("cp.async.commit_group;\n");
    };

    // prologue: chunks 0,1,2 into stages 0,1,2  (chunk c lives in stage c%3)
    issue_chunk(0, 0);
    issue_chunk(KC, 1);
    issue_chunk(2 * KC, 2);

    int stage = 0;
#pragma unroll
    for (int i = 0; i < 8; ++i) {
        asm volatile("cp.async.wait_group 2;\n" ::: "memory");
        __syncthreads();

        const __half* Ab = Ah + stage * ABUFH;
        const __half* Bb = Bh + stage * BBUFH;
#pragma unroll
        for (int ks = 0; ks < 2; ++ks) {
            uint32_t a[4][4];
#pragma unroll
            for (int mt = 0; mt < 4; ++mt) {
                const int row = wm + mt * 16 + (lane & 15);
                const int kh  = ks * 16 + (lane >> 4) * 8;
                ldsm_x4(a[mt], (uint32_t)__cvta_generic_to_shared(Ab + row * ASPH + kh));
            }
            uint32_t bf[8][2];
#pragma unroll
            for (int p = 0; p < 4; ++p) {
                const int r    = lane & 7;
                const int seg  = lane >> 3;
                const int krow = ks * 16 + (seg & 1) * 8 + r;
                const int col  = wn + p * 16 + (seg >> 1) * 8;
                uint32_t t[4];
                ldsm_x4_t(t, (uint32_t)__cvta_generic_to_shared(Bb + krow * BSPH + col));
                bf[2 * p][0]     = t[0];
                bf[2 * p][1]     = t[1];
                bf[2 * p + 1][0] = t[2];
                bf[2 * p + 1][1] = t[3];
            }
#pragma unroll
            for (int mt = 0; mt < 4; ++mt)
#pragma unroll
                for (int nt = 0; nt < 8; ++nt)
                    mma_f16(acc[mt][nt], a[mt], bf[nt]);
        }
        __syncthreads();   // all reads of 'stage' done before refill

        if (i + 3 < 8) issue_chunk((i + 3) * KC, stage);
        else           asm volatile("cp.async.commit_group;\n");  // keep group count uniform
        stage = (stage + 1 == NSTG) ? 0 : stage + 1;
    }

    // ---- epilogue: relu (v rows), rn-to-fp16, scatter pixel-major ----
    const int g   = lane >> 2;
    const int tig = lane & 3;
    const bool isv = (m0 >= 512);
#pragma unroll
    for (int mm = 0; mm < 4; ++mm) {
#pragma unroll
        for (int nt = 0; nt < 8; ++nt) {
            const int ncol = n0 + wn + nt * 8 + 2 * tig;
            const int mrow = m0 + wm + mm * 16 + g;
            float v0 = acc[mm][nt][0];
            float v1 = acc[mm][nt][1];
            float v2 = acc[mm][nt][2];
            float v3 = acc[mm][nt][3];
            if (isv) {
                v0 = fmaxf(v0, 0.f); v1 = fmaxf(v1, 0.f);
                v2 = fmaxf(v2, 0.f); v3 = fmaxf(v3, 0.f);
            }
            if (ncol < HW) {
                __half* d0 = g_buf + ((size_t)b * HW + ncol) * OCH + mrow;
                d0[0] = __float2half_rn(v0);
                d0[8] = __float2half_rn(v2);
            }
            if (ncol + 1 < HW) {
                __half* d1 = g_buf + ((size_t)b * HW + ncol + 1) * OCH + mrow;
                d1[0] = __float2half_rn(v1);
                d1[8] = __float2half_rn(v3);
            }
        }
    }
}

// ---------------------------------------------------------------------------
// Kernel 2: fp16 tensor-core window attention, register-resident softmax.
// (unchanged from previous round)
// ---------------------------------------------------------------------------
#define HQS 72
#define ATTN_SMEM_BYTES (3 * 64 * HQS * 2 + NTOK * 4 + 16)

__global__ __launch_bounds__(128) void attn_kernel()
{
    extern __shared__ char smraw[];
    __half* s_q = reinterpret_cast<__half*>(smraw);
    __half* s_k = s_q + 64 * HQS;
    __half* s_v = s_k + 64 * HQS;
    int*    s_p = reinterpret_cast<int*>(s_v + 64 * HQS);

    const int b    = blockIdx.z;
    const int h    = blockIdx.y & 3;
    const int part = blockIdx.y >> 2;
    const int win  = blockIdx.x;
    const int j1   = win >> 3;
    const int j2   = win & 7;
    const int tid  = threadIdx.x;
    const int lane = tid & 31;
    const int wid  = tid >> 5;
    const int g    = lane >> 2;
    const int tig  = lane & 3;
    const int wr   = wid * 16;

    if (tid < NTOK) {
        int h1 = tid / 7, w1 = tid - h1 * 7;
        int hh, ww;
        if (part == 0) { hh = h1 * 8 + j1; ww = w1 * 8 + j2; }   // remote
        else           { hh = j1 * 7 + h1; ww = j2 * 7 + w1; }   // close
        s_p[tid] = hh * WIMG + ww;
    }
    {
        uint32_t* vz = reinterpret_cast<uint32_t*>(s_v + NTOK * HQS);
        for (int i = tid; i < 15 * HQS / 2; i += 128) vz[i] = 0;
    }
    __syncthreads();

    {
        const __half* base = g_buf + (size_t)b * HW * OCH + h * 64;
        for (int idx = tid; idx < NTOK * 24; idx += 128) {
            const int pix = idx / 24;
            const int r   = idx - pix * 24;
            const int seg = r >> 3;
            const int ch  = r & 7;
            const __half* src = base + (size_t)s_p[pix] * OCH + seg * 256 + ch * 8;
            __half* dsth = (seg == 0 ? s_q : seg == 1 ? s_k : s_v) + pix * HQS + ch * 8;
            cp16(dsth, src);
        }
        asm volatile("cp.async.commit_group;\n");
        asm volatile("cp.async.wait_group 0;\n" ::: "memory");
    }
    __syncthreads();

    float cS[8][4];
#pragma unroll
    for (int nt = 0; nt < 8; ++nt)
#pragma unroll
        for (int r = 0; r < 4; ++r) cS[nt][r] = 0.f;

#pragma unroll
    for (int ks = 0; ks < 4; ++ks) {
        uint32_t a[4];
        ldsm_x4(a, (uint32_t)__cvta_generic_to_shared(
            s_q + (wr + (lane & 15)) * HQS + ks * 16 + (lane >> 4) * 8));
        const int r  = lane & 7;
        const int s2 = lane >> 3;
#pragma unroll
        for (int ng = 0; ng < 4; ++ng) {
            uint32_t t[4];
            ldsm_x4(t, (uint32_t)__cvta_generic_to_shared(
                s_k + (ng * 16 + (s2 >> 1) * 8 + r) * HQS + ks * 16 + (s2 & 1) * 8));
            mma_f16(cS[2 * ng],     a, t);
            mma_f16(cS[2 * ng + 1], a, t + 2);
        }
    }

#pragma unroll
    for (int nt = 0; nt < 8; ++nt) {
        const int c0 = nt * 8 + 2 * tig;
        const bool ok0 = (c0 <= 48);
        const bool ok1 = (c0 + 1 <= 48);
        cS[nt][0] = ok0 ? cS[nt][0] * 0.125f : -1e30f;
        cS[nt][1] = ok1 ? cS[nt][1] * 0.125f : -1e30f;
        cS[nt][2] = ok0 ? cS[nt][2] * 0.125f : -1e30f;
        cS[nt][3] = ok1 ? cS[nt][3] * 0.125f : -1e30f;
    }
    float mx0 = -1e30f, mx1 = -1e30f;
#pragma unroll
    for (int nt = 0; nt < 8; ++nt) {
        mx0 = fmaxf(mx0, fmaxf(cS[nt][0], cS[nt][1]));
        mx1 = fmaxf(mx1, fmaxf(cS[nt][2], cS[nt][3]));
    }
    mx0 = fmaxf(mx0, __shfl_xor_sync(0xffffffffu, mx0, 1));
    mx0 = fmaxf(mx0, __shfl_xor_sync(0xffffffffu, mx0, 2));
    mx1 = fmaxf(mx1, __shfl_xor_sync(0xffffffffu, mx1, 1));
    mx1 = fmaxf(mx1, __shfl_xor_sync(0xffffffffu, mx1, 2));
    float s0 = 0.f, s1 = 0.f;
#pragma unroll
    for (int nt = 0; nt < 8; ++nt) {
        cS[nt][0] = __expf(cS[nt][0] - mx0);
        cS[nt][1] = __expf(cS[nt][1] - mx0);
        cS[nt][2] = __expf(cS[nt][2] - mx1);
        cS[nt][3] = __expf(cS[nt][3] - mx1);
        s0 += cS[nt][0] + cS[nt][1];
        s1 += cS[nt][2] + cS[nt][3];
    }
    s0 += __shfl_xor_sync(0xffffffffu, s0, 1);
    s0 += __shfl_xor_sync(0xffffffffu, s0, 2);
    s1 += __shfl_xor_sync(0xffffffffu, s1, 1);
    s1 += __shfl_xor_sync(0xffffffffu, s1, 2);
    const float i0 = 1.f / s0;
    const float i1 = 1.f / s1;

    uint32_t aP[4][4];
#pragma unroll
    for (int ks = 0; ks < 4; ++ks) {
        aP[ks][0] = pack_f16x2(cS[2 * ks][0] * i0,     cS[2 * ks][1] * i0);
        aP[ks][1] = pack_f16x2(cS[2 * ks][2] * i1,     cS[2 * ks][3] * i1);
        aP[ks][2] = pack_f16x2(cS[2 * ks + 1][0] * i0, cS[2 * ks + 1][1] * i0);
        aP[ks][3] = pack_f16x2(cS[2 * ks + 1][2] * i1, cS[2 * ks + 1][3] * i1);
    }

    {
        float cO[8][4];
#pragma unroll
        for (int nt = 0; nt < 8; ++nt)
#pragma unroll
            for (int r = 0; r < 4; ++r) cO[nt][r] = 0.f;

#pragma unroll
        for (int ks = 0; ks < 4; ++ks) {
            const int r  = lane & 7;
            const int s2 = lane >> 3;
#pragma unroll
            for (int p = 0; p < 4; ++p) {
                uint32_t t[4];
                ldsm_x4_t(t, (uint32_t)__cvta_generic_to_shared(
                    s_v + (ks * 16 + (s2 & 1) * 8 + r) * HQS + p * 16 + (s2 >> 1) * 8));
                mma_f16(cO[2 * p],     aP[ks], t);
                mma_f16(cO[2 * p + 1], aP[ks], t + 2);
            }
        }

        __half* obuf = (part == 0) ? o_r : o_c;
        const int r0 = wr + g;
        const int r1 = r0 + 8;
#pragma unroll
        for (int nt = 0; nt < 8; ++nt) {
            const int d = h * 64 + nt * 8 + 2 * tig;
            if (r0 < NTOK) {
                *reinterpret_cast<uint32_t*>(&obuf[((size_t)b * HW + s_p[r0]) * 256 + d]) =
                    pack_f16x2(cO[nt][0], cO[nt][1]);
            }
            if (r1 < NTOK) {
                *reinterpret_cast<uint32_t*>(&obuf[((size_t)b * HW + s_p[r1]) * 256 + d]) =
                    pack_f16x2(cO[nt][2], cO[nt][3]);
            }
        }
    }
}

// ---------------------------------------------------------------------------
// Kernel 3: merge + transpose: out[b][c][p] = o_r[b][p][c] + o_c[b][p][c]
// ---------------------------------------------------------------------------
__global__ __launch_bounds__(256) void merge_kernel(float* __restrict__ out)
{
    __shared__ float tile[32][33];
    const int b  = blockIdx.z;
    const int c0 = blockIdx.y * 32;
    const int p0 = blockIdx.x * 32;
    const int tx = threadIdx.x & 31;
    const int ty = threadIdx.x >> 5;

#pragma unroll
    for (int i = 0; i < 4; ++i) {
        const int p = p0 + ty + i * 8;
        const size_t off = ((size_t)b * HW + p) * 256 + c0 + tx;
        tile[ty + i * 8][tx] = __half2float(o_r[off]) + __half2float(o_c[off]);
    }
    __syncthreads();
#pragma unroll
    for (int i = 0; i < 4; ++i) {
        const int c = c0 + ty + i * 8;
        out[((size_t)b * 256 + c) * HW + p0 + tx] = tile[tx][ty + i * 8];
    }
}

// ---------------------------------------------------------------------------
extern "C" void kernel_launch(void* const* d_in, const int* in_sizes, int n_in,
                              void* d_out, int out_size)
{
    const float* x    = (const float*)d_in[0];
    const float* qk_w = (const float*)d_in[1];
    const float* v_w  = (const float*)d_in[2];
    float* out = (float*)d_out;

    pack_w_kernel<<<96, 256>>>(qk_w, v_w);                 // 768*256/8/256
    pack_x_kernel<<<12544, 256>>>(x);                      // 32*256*3136/8/256

    cudaFuncSetAttribute(conv_kernel, cudaFuncAttributeMaxDynamicSharedMemorySize, CONV_SMEM_BYTES);
    conv_kernel<<<dim3(13, 6, 32), 256, CONV_SMEM_BYTES>>>();

    cudaFuncSetAttribute(attn_kernel, cudaFuncAttributeMaxDynamicSharedMemorySize, ATTN_SMEM_BYTES);
    attn_kernel<<<dim3(64, 8, 32), 128, ATTN_SMEM_BYTES>>>();

    merge_kernel<<<dim3(98, 8, 32), 256>>>(out);
}